// round 7
// baseline (speedup 1.0000x reference)
#include <cuda_runtime.h>
#include <cuda_fp16.h>
#include <math.h>
#include <stdint.h>
#include <stddef.h>

// Problem constants
#define BB   16384            // batch / paths
#define DD   256              // embedding dim
#define HH   512              // hidden dim
#define TT   768              // text dim
#define RR   32               // relation classes
#define G3H  1536             // 3*H

typedef __half  fp16;
typedef __half2 fp162;

// ---------------------------------------------------------------------------
// Scratch. "_e" buffers: hi/lo extended fp16 activations: logical [M,K] fp32
// stored as [M,2K]: cols [0,K)=hi, [K,2K)=lo. Weights: PLAIN fp16 [K,N].
// ---------------------------------------------------------------------------
__device__ __align__(128) float g_tx   [(size_t)BB * DD];
__device__ __align__(128) float g_state[(size_t)4 * BB * HH];
__device__ __align__(128) float g_msg  [(size_t)3 * BB * HH];
__device__ __align__(128) float g_gi   [(size_t)3 * BB * G3H];
__device__ __align__(128) float g_gh   [(size_t)4 * BB * G3H];
__device__ __align__(128) float g_hh   [(size_t)BB * HH];

__device__ __align__(128) fp16 g_text_e  [(size_t)BB * 2 * TT];
__device__ __align__(128) fp16 g_emb4_e  [(size_t)4 * BB * 2 * DD];
__device__ __align__(128) fp16 g_state_e [(size_t)4 * BB * 2 * HH];
__device__ __align__(128) fp16 g_diff_e  [(size_t)3 * BB * 2 * HH];
__device__ __align__(128) fp16 g_hidm_e  [(size_t)3 * BB * 2 * HH];
__device__ __align__(128) fp16 g_hida_e  [(size_t)3 * BB * HH];        // 2*(H/2)
__device__ __align__(128) fp16 g_msgatt_e[(size_t)3 * BB * 2 * HH];
__device__ __align__(128) fp16 g_ddv_e   [(size_t)BB * 2 * HH];

// plain fp16 weights [K,N]
__device__ __align__(128) fp16 g_textW_h [(size_t)TT * DD];
__device__ __align__(128) fp16 g_projW_h [(size_t)DD * HH];
__device__ __align__(128) fp16 g_msgW1_h [2][(size_t)HH * HH];
__device__ __align__(128) fp16 g_msgW2_h [2][(size_t)HH * HH];
__device__ __align__(128) fp16 g_attW1_h [2][(size_t)HH * (HH/2)];
__device__ __align__(128) fp16 g_attW2_h [2][(size_t)(HH/2) * HH];
__device__ __align__(128) fp16 g_Wih_h   [2][(size_t)HH * G3H];
__device__ __align__(128) fp16 g_Whh_h   [2][(size_t)HH * G3H];
__device__ __align__(128) fp16 g_headW1_h[(size_t)HH * HH];

// ---------------------------------------------------------------------------
// Small helpers
// ---------------------------------------------------------------------------
__device__ __forceinline__ uint32_t smem_u32(const void* p) {
    return (uint32_t)__cvta_generic_to_shared(p);
}
__device__ __forceinline__ void cp16c(void* s, const void* g) {
    asm volatile("cp.async.cg.shared.global [%0], [%1], 16;\n"
                 :: "r"(smem_u32(s)), "l"(g));
}
__device__ __forceinline__ void cp_commit() {
    asm volatile("cp.async.commit_group;\n");
}
__device__ __forceinline__ void cp_wait0() {
    asm volatile("cp.async.wait_group 0;\n");
}
__device__ __forceinline__ void cp_wait1() {
    asm volatile("cp.async.wait_group 1;\n");
}
#define LDSM_X4(r0,r1,r2,r3,addr) \
    asm volatile("ldmatrix.sync.aligned.m8n8.x4.shared.b16 {%0,%1,%2,%3}, [%4];" \
        : "=r"(r0),"=r"(r1),"=r"(r2),"=r"(r3) : "r"(addr))
#define LDSM_X4T(r0,r1,r2,r3,addr) \
    asm volatile("ldmatrix.sync.aligned.m8n8.x4.trans.shared.b16 {%0,%1,%2,%3}, [%4];" \
        : "=r"(r0),"=r"(r1),"=r"(r2),"=r"(r3) : "r"(addr))
__device__ __forceinline__ void mma16816(float* d, const uint32_t* a, const uint32_t* b) {
    asm volatile(
        "mma.sync.aligned.m16n8k16.row.col.f32.f16.f16.f32 "
        "{%0,%1,%2,%3},{%4,%5,%6,%7},{%8,%9},{%0,%1,%2,%3};"
        : "+f"(d[0]), "+f"(d[1]), "+f"(d[2]), "+f"(d[3])
        : "r"(a[0]), "r"(a[1]), "r"(a[2]), "r"(a[3]), "r"(b[0]), "r"(b[1]));
}

__device__ __forceinline__ float sigf(float x) { return 1.f / (1.f + expf(-x)); }

// write 4 fp32 values as hi/lo fp16 quads
__device__ __forceinline__ void hilo4(float4 v, fp16* hp, fp16* lp) {
    fp16 hx = __float2half_rn(v.x), hy = __float2half_rn(v.y);
    fp16 hz = __float2half_rn(v.z), hw = __float2half_rn(v.w);
    ((fp162*)hp)[0] = __halves2half2(hx, hy);
    ((fp162*)hp)[1] = __halves2half2(hz, hw);
    ((fp162*)lp)[0] = __halves2half2(
        __float2half_rn(v.x - __half2float(hx)),
        __float2half_rn(v.y - __half2float(hy)));
    ((fp162*)lp)[1] = __halves2half2(
        __float2half_rn(v.z - __half2float(hz)),
        __float2half_rn(v.w - __half2float(hw)));
}

// ---------------------------------------------------------------------------
// fp16 tensor-core GEMM, 2-pass hi/lo on A only.
// A: [M, 2K] ext fp16, W: [K, N] plain fp16. Result = fp32 (Ahi+Alo)@W.
// EPI: 0 = +bias, 1 = relu(+bias), 2 = relu(+bias + aux[m>>14][n]),
//      3 = aux[m,n] * sigmoid(+bias)
// OUT bit0: fp32 C[m*N+n]; bit1: ext fp16 E[m*2N + (n | N+n)]
// CTA tile 128(M) x 256(N), K-chunk 64, 3-stage cp.async pipeline.
// 512 threads = 16 warps: wm = warp&3 (M), wn = warp>>2 (N). Warp tile 32x64.
// ---------------------------------------------------------------------------
#define SA_STRIDE 72     // 64 + 8 pad (halves)
#define SB_STRIDE 264    // 256 + 8 pad (halves)
#define SA_HALVES (3 * 128 * SA_STRIDE)
#define SB_HALVES (3 * 64 * SB_STRIDE)
#define GSM_BYTES ((SA_HALVES + SB_HALVES) * 2)

template<int EPI, int OUT>
__global__ __launch_bounds__(512)
void hgemm_k(const fp16* __restrict__ A, const fp16* __restrict__ W,
             float* __restrict__ C, fp16* __restrict__ E,
             const float* __restrict__ bias, const float* __restrict__ aux,
             int M, int N, int K)
{
    extern __shared__ __align__(16) fp16 smem[];
    fp16* sA = smem;               // [3][128][SA_STRIDE]
    fp16* sB = smem + SA_HALVES;   // [3][64][SB_STRIDE]

    const int tid = threadIdx.x;
    const int m0 = blockIdx.y * 128, n0 = blockIdx.x * 256;
    const int warp = tid >> 5, lane = tid & 31;
    const int wm = warp & 3, wn = warp >> 2;

    const int kIters = K >> 6;      // K-chunks of 64
    const int T = 2 * kIters;       // 2 passes: Ahi*W then Alo*W
    const size_t lda = 2 * (size_t)K;

    float acc[2][8][4];
#pragma unroll
    for (int i = 0; i < 2; i++)
#pragma unroll
        for (int j = 0; j < 8; j++)
#pragma unroll
            for (int q = 0; q < 4; q++) acc[i][j][q] = 0.f;

    const int arow = tid >> 2, ac0 = (tid & 3) * 16;   // A: 128r x 64c, 2x16B/thr
    const int brow = tid >> 3, bc0 = (tid & 7) * 32;   // B: 64r x 256c, 4x16B/thr

    auto load_tile = [&](int it, int buf) {
        int p  = it / kIters;                 // 0: hi, 1: lo
        int kb = it - p * kIters;
        int k0 = kb << 6;
        int aoff = (p == 1) ? K : 0;
        const fp16* ga = A + (size_t)(m0 + arow) * lda + aoff + k0 + ac0;
        fp16* sa = sA + (buf * 128 + arow) * SA_STRIDE + ac0;
        cp16c(sa,     ga);
        cp16c(sa + 8, ga + 8);
        const fp16* gb = W + (size_t)(k0 + brow) * N + n0 + bc0;
        fp16* sb = sB + (buf * 64 + brow) * SB_STRIDE + bc0;
        cp16c(sb,      gb);
        cp16c(sb + 8,  gb + 8);
        cp16c(sb + 16, gb + 16);
        cp16c(sb + 24, gb + 24);
        cp_commit();
    };

    load_tile(0, 0);
    if (T > 1) load_tile(1, 1);

    for (int it = 0; it < T; ++it) {
        const int buf = it % 3;
        if (it + 1 < T) cp_wait1(); else cp_wait0();
        __syncthreads();

#pragma unroll
        for (int kk = 0; kk < 4; ++kk) {
            uint32_t afrag[2][4];
#pragma unroll
            for (int mt = 0; mt < 2; ++mt) {
                int r = wm * 32 + mt * 16 + (lane & 15);
                int c = kk * 16 + ((lane >> 4) << 3);
                LDSM_X4(afrag[mt][0], afrag[mt][1], afrag[mt][2], afrag[mt][3],
                        smem_u32(sA + (buf * 128 + r) * SA_STRIDE + c));
            }
            uint32_t bfrag[8][2];
#pragma unroll
            for (int tp = 0; tp < 4; ++tp) {
                int g = lane >> 3, lr = lane & 7;
                int row = kk * 16 + ((g & 1) << 3) + lr;
                int col = wn * 64 + tp * 16 + ((g >> 1) << 3);
                uint32_t r0, r1, r2, r3;
                LDSM_X4T(r0, r1, r2, r3,
                         smem_u32(sB + (buf * 64 + row) * SB_STRIDE + col));
                bfrag[tp * 2][0] = r0;     bfrag[tp * 2][1] = r1;
                bfrag[tp * 2 + 1][0] = r2; bfrag[tp * 2 + 1][1] = r3;
            }
#pragma unroll
            for (int mt = 0; mt < 2; ++mt)
#pragma unroll
                for (int nt = 0; nt < 8; ++nt)
                    mma16816(acc[mt][nt], afrag[mt], bfrag[nt]);
        }
        __syncthreads();
        if (it + 2 < T) load_tile(it + 2, (it + 2) % 3);
    }

    // epilogue
    const int r0 = lane >> 2, c0 = (lane & 3) * 2;
#pragma unroll
    for (int mt = 0; mt < 2; ++mt) {
#pragma unroll
        for (int half = 0; half < 2; ++half) {
            const int m = m0 + wm * 32 + mt * 16 + r0 + half * 8;
            const int et = m >> 14;
#pragma unroll
            for (int nt = 0; nt < 8; ++nt) {
                const int n = n0 + wn * 64 + nt * 8 + c0;
                float v0 = acc[mt][nt][half * 2 + 0] + bias[n];
                float v1 = acc[mt][nt][half * 2 + 1] + bias[n + 1];
                if (EPI == 2) {
                    v0 += aux[(size_t)et * N + n];
                    v1 += aux[(size_t)et * N + n + 1];
                }
                if (EPI == 1 || EPI == 2) { v0 = fmaxf(v0, 0.f); v1 = fmaxf(v1, 0.f); }
                if (EPI == 3) {
                    v0 = aux[(size_t)m * N + n]     * sigf(v0);
                    v1 = aux[(size_t)m * N + n + 1] * sigf(v1);
                }
                if (OUT & 1) {
                    float2 fv = {v0, v1};
                    *(float2*)&C[(size_t)m * N + n] = fv;
                }
                if (OUT & 2) {
                    fp16 h0 = __float2half_rn(v0), h1 = __float2half_rn(v1);
                    fp16* base = E + (size_t)m * 2 * N;
                    *(fp162*)(base + n) = __halves2half2(h0, h1);
                    *(fp162*)(base + N + n) = __halves2half2(
                        __float2half_rn(v0 - __half2float(h0)),
                        __float2half_rn(v1 - __half2float(h1)));
                }
            }
        }
    }
}

// ---------------------------------------------------------------------------
// Conversion / elementwise kernels
// ---------------------------------------------------------------------------

// fp32 W[K,N] -> plain fp16 [K,N]
__global__ void cvt_w_k(const float* __restrict__ W, fp16* __restrict__ E, int KN)
{
    int gid = blockIdx.x * blockDim.x + threadIdx.x;
    if (gid * 4 >= KN) return;
    float4 v = *(const float4*)(W + (size_t)gid * 4);
    fp16* p = E + (size_t)gid * 4;
    ((fp162*)p)[0] = __halves2half2(__float2half_rn(v.x), __float2half_rn(v.y));
    ((fp162*)p)[1] = __halves2half2(__float2half_rn(v.z), __float2half_rn(v.w));
}

// GRU weight (3H,H) row-major -> transposed plain fp16 [H, 3H]
__global__ void cvt_w_gru_k(const float* __restrict__ Wg, fp16* __restrict__ E)
{
    int gid = blockIdx.x * blockDim.x + threadIdx.x;     // over H*3H
    if (gid >= HH * G3H) return;
    int k = gid / G3H, j = gid - k * G3H;
    E[gid] = __float2half_rn(Wg[(size_t)j * HH + k]);
}

// text_ab fp32 [B,T] -> ext [B,2T]
__global__ void cvt_text_k(const float* __restrict__ X)
{
    int gid = blockIdx.x * blockDim.x + threadIdx.x;     // B * T/4
    if (gid >= BB * (TT / 4)) return;
    int m = gid / (TT / 4), q = gid - m * (TT / 4);
    float4 v = *(const float4*)(X + (size_t)m * TT + q * 4);
    fp16* base = g_text_e + (size_t)m * 2 * TT;
    hilo4(v, base + q * 4, base + TT + q * 4);
}

// gather node embeddings (event gets +tx) -> ext [4B, 2D]
__global__ void gather_emb_k(const int* __restrict__ a, const int* __restrict__ ev,
                             const int* __restrict__ b, const int* __restrict__ c,
                             const float* __restrict__ ent)
{
    int gid = blockIdx.x * blockDim.x + threadIdx.x;     // 4B * 64
    if (gid >= 4 * BB * (DD / 4)) return;
    int row = gid >> 6, c4 = (gid & 63) * 4;
    int sel = row >> 14, r = row & (BB - 1);
    int id = (sel == 0) ? a[r] : (sel == 1) ? ev[r] : (sel == 2) ? b[r] : c[r];
    float4 v = *(const float4*)(ent + (size_t)id * DD + c4);
    if (sel == 1) {
        float4 tv = *(const float4*)(g_tx + (size_t)r * DD + c4);
        v.x += tv.x; v.y += tv.y; v.z += tv.z; v.w += tv.w;
    }
    fp16* base = g_emb4_e + (size_t)row * 2 * DD;
    hilo4(v, base + c4, base + DD + c4);
}

// diff = state[src] - state[dst] -> ext [3B, 2H]
__global__ void diff_cvt_k()
{
    int gid = blockIdx.x * blockDim.x + threadIdx.x;     // 3B * 128
    if (gid >= 3 * BB * (HH / 4)) return;
    int row = gid >> 7, c = (gid & 127) * 4;
    int src = (row < 2 * BB) ? row : row - BB;
    float4 s = *(const float4*)(g_state + (size_t)src * HH + c);
    float4 d = *(const float4*)(g_state + (size_t)(row + BB) * HH + c);
    s.x -= d.x; s.y -= d.y; s.z -= d.z; s.w -= d.w;
    fp16* base = g_diff_e + (size_t)row * 2 * HH;
    hilo4(s, base + c, base + HH + c);
}

// state = relu(state), refresh ext
__global__ void relu_state_k()
{
    int gid = blockIdx.x * blockDim.x + threadIdx.x;     // 4B * 128
    if (gid >= 4 * BB * (HH / 4)) return;
    int row = gid >> 7, c = (gid & 127) * 4;
    float4 v = *(float4*)(g_state + (size_t)row * HH + c);
    v.x = fmaxf(v.x, 0.f); v.y = fmaxf(v.y, 0.f);
    v.z = fmaxf(v.z, 0.f); v.w = fmaxf(v.w, 0.f);
    *(float4*)(g_state + (size_t)row * HH + c) = v;
    fp16* base = g_state_e + (size_t)row * 2 * HH;
    hilo4(v, base + c, base + HH + c);
}

// GRU elementwise update; writes state fp32 + ext
__global__ void gru_k(const float* __restrict__ bih)
{
    int gid = blockIdx.x * blockDim.x + threadIdx.x;     // 4B * 128
    if (gid >= 4 * BB * (HH / 4)) return;
    int m = gid >> 7, c = (gid & 127) * 4;

    const float* ghr = g_gh + (size_t)m * G3H;
    float4 hr = *(const float4*)(ghr + c);
    float4 hz = *(const float4*)(ghr + HH + c);
    float4 hn = *(const float4*)(ghr + 2 * HH + c);

    float4 ir, iz, in_;
    if (m < BB) {
        ir  = *(const float4*)(bih + c);
        iz  = *(const float4*)(bih + HH + c);
        in_ = *(const float4*)(bih + 2 * HH + c);
    } else {
        const float* gir = g_gi + (size_t)(m - BB) * G3H;
        ir  = *(const float4*)(gir + c);
        iz  = *(const float4*)(gir + HH + c);
        in_ = *(const float4*)(gir + 2 * HH + c);
    }
    float4 old = *(const float4*)(g_state + (size_t)m * HH + c);

    float4 out;
    { float r = sigf(ir.x + hr.x), z = sigf(iz.x + hz.x);
      float n = tanhf(in_.x + r * hn.x); out.x = (1.f - z) * n + z * old.x; }
    { float r = sigf(ir.y + hr.y), z = sigf(iz.y + hz.y);
      float n = tanhf(in_.y + r * hn.y); out.y = (1.f - z) * n + z * old.y; }
    { float r = sigf(ir.z + hr.z), z = sigf(iz.z + hz.z);
      float n = tanhf(in_.z + r * hn.z); out.z = (1.f - z) * n + z * old.z; }
    { float r = sigf(ir.w + hr.w), z = sigf(iz.w + hz.w);
      float n = tanhf(in_.w + r * hn.w); out.w = (1.f - z) * n + z * old.w; }

    *(float4*)(g_state + (size_t)m * HH + c) = out;
    fp16* base = g_state_e + (size_t)m * 2 * HH;
    hilo4(out, base + c, base + HH + c);
}

// head diff -> ext [B, 2H]
__global__ void dd_cvt_k()
{
    int gid = blockIdx.x * blockDim.x + threadIdx.x;     // B * 128
    if (gid >= BB * (HH / 4)) return;
    int row = gid >> 7, c = (gid & 127) * 4;
    float4 a = *(const float4*)(g_state + (size_t)row * HH + c);
    float4 b = *(const float4*)(g_state + (size_t)(row + 2 * BB) * HH + c);
    a.x -= b.x; a.y -= b.y; a.z -= b.z; a.w -= b.w;
    fp16* base = g_ddv_e + (size_t)row * 2 * HH;
    hilo4(a, base + c, base + HH + c);
}

// final head: out[B,32] = hh[B,512] @ W2[512,32] + b2 (fp32, tiny)
__global__ void head2_k(const float* __restrict__ W2, const float* __restrict__ b2,
                        float* __restrict__ out)
{
    int r = threadIdx.x >> 5, col = threadIdx.x & 31;
    int row = blockIdx.x * 8 + r;
    const float* h = g_hh + (size_t)row * HH;
    float acc = b2[col];
#pragma unroll 8
    for (int k = 0; k < HH; k++)
        acc = fmaf(h[k], W2[k * RR + col], acc);
    out[(size_t)row * RR + col] = acc;
}

// ---------------------------------------------------------------------------
// Host launch
// ---------------------------------------------------------------------------
static void launch_hgemm(int epi, int out, const fp16* A, const fp16* W,
                         float* C, fp16* E, const float* bias, const float* aux,
                         int M, int N, int K)
{
    dim3 grid(N / 256, M / 128);
    if (epi == 1 && out == 1) {
        cudaFuncSetAttribute(hgemm_k<1, 1>, cudaFuncAttributeMaxDynamicSharedMemorySize, GSM_BYTES);
        hgemm_k<1, 1><<<grid, 512, GSM_BYTES>>>(A, W, C, E, bias, aux, M, N, K);
    } else if (epi == 1 && out == 3) {
        cudaFuncSetAttribute(hgemm_k<1, 3>, cudaFuncAttributeMaxDynamicSharedMemorySize, GSM_BYTES);
        hgemm_k<1, 3><<<grid, 512, GSM_BYTES>>>(A, W, C, E, bias, aux, M, N, K);
    } else if (epi == 2 && out == 2) {
        cudaFuncSetAttribute(hgemm_k<2, 2>, cudaFuncAttributeMaxDynamicSharedMemorySize, GSM_BYTES);
        hgemm_k<2, 2><<<grid, 512, GSM_BYTES>>>(A, W, C, E, bias, aux, M, N, K);
    } else if (epi == 0 && out == 1) {
        cudaFuncSetAttribute(hgemm_k<0, 1>, cudaFuncAttributeMaxDynamicSharedMemorySize, GSM_BYTES);
        hgemm_k<0, 1><<<grid, 512, GSM_BYTES>>>(A, W, C, E, bias, aux, M, N, K);
    } else if (epi == 3 && out == 2) {
        cudaFuncSetAttribute(hgemm_k<3, 2>, cudaFuncAttributeMaxDynamicSharedMemorySize, GSM_BYTES);
        hgemm_k<3, 2><<<grid, 512, GSM_BYTES>>>(A, W, C, E, bias, aux, M, N, K);
    }
}

extern "C" void kernel_launch(void* const* d_in, const int* in_sizes, int n_in,
                              void* d_out, int out_size)
{
    const int*   a_ids   = (const int*)  d_in[0];
    const int*   ev_ids  = (const int*)  d_in[1];
    const int*   b_ids   = (const int*)  d_in[2];
    const int*   c_ids   = (const int*)  d_in[3];
    const float* text_ab = (const float*)d_in[4];
    const float* ent     = (const float*)d_in[5];
    const float* text_W  = (const float*)d_in[6];
    const float* text_b  = (const float*)d_in[7];
    const float* proj_W  = (const float*)d_in[8];
    const float* proj_b  = (const float*)d_in[9];
    const float* msg_W1  = (const float*)d_in[10];
    const float* msg_b1  = (const float*)d_in[11];
    const float* msg_W2  = (const float*)d_in[12];
    const float* msg_b2  = (const float*)d_in[13];
    const float* att_W1  = (const float*)d_in[14];
    const float* att_b1  = (const float*)d_in[15];
    const float* att_W2  = (const float*)d_in[16];
    const float* att_b2  = (const float*)d_in[17];
    const float* gru_Wih = (const float*)d_in[18];
    const float* gru_Whh = (const float*)d_in[19];
    const float* gru_bih = (const float*)d_in[20];
    const float* gru_bhh = (const float*)d_in[21];
    const float* head_W1 = (const float*)d_in[22];
    const float* head_b1 = (const float*)d_in[23];
    const float* head_W2 = (const float*)d_in[24];
    const float* head_b2 = (const float*)d_in[25];
    float* out = (float*)d_out;

    float *tx, *state, *msgp, *gi, *gh, *hh;
    fp16 *text_e, *emb4_e, *state_e, *diff_e, *hidm_e, *hida_e, *msgatt_e, *ddv_e;
    fp16 *textW, *projW, *msgW1h, *msgW2h, *attW1h, *attW2h, *Wihh, *Whhh, *headW1h;
    cudaGetSymbolAddress((void**)&tx,       g_tx);
    cudaGetSymbolAddress((void**)&state,    g_state);
    cudaGetSymbolAddress((void**)&msgp,     g_msg);
    cudaGetSymbolAddress((void**)&gi,       g_gi);
    cudaGetSymbolAddress((void**)&gh,       g_gh);
    cudaGetSymbolAddress((void**)&hh,       g_hh);
    cudaGetSymbolAddress((void**)&text_e,   g_text_e);
    cudaGetSymbolAddress((void**)&emb4_e,   g_emb4_e);
    cudaGetSymbolAddress((void**)&state_e,  g_state_e);
    cudaGetSymbolAddress((void**)&diff_e,   g_diff_e);
    cudaGetSymbolAddress((void**)&hidm_e,   g_hidm_e);
    cudaGetSymbolAddress((void**)&hida_e,   g_hida_e);
    cudaGetSymbolAddress((void**)&msgatt_e, g_msgatt_e);
    cudaGetSymbolAddress((void**)&ddv_e,    g_ddv_e);
    cudaGetSymbolAddress((void**)&textW,    g_textW_h);
    cudaGetSymbolAddress((void**)&projW,    g_projW_h);
    cudaGetSymbolAddress((void**)&msgW1h,   g_msgW1_h);
    cudaGetSymbolAddress((void**)&msgW2h,   g_msgW2_h);
    cudaGetSymbolAddress((void**)&attW1h,   g_attW1_h);
    cudaGetSymbolAddress((void**)&attW2h,   g_attW2_h);
    cudaGetSymbolAddress((void**)&Wihh,     g_Wih_h);
    cudaGetSymbolAddress((void**)&Whhh,     g_Whh_h);
    cudaGetSymbolAddress((void**)&headW1h,  g_headW1_h);

    auto cvw = [](const float* W, fp16* E, int KN) {
        cvt_w_k<<<(KN / 4 + 255) / 256, 256>>>(W, E, KN);
    };

    // ---- weight conversions (plain fp16) ----
    cvw(text_W, textW, TT * DD);
    cvw(proj_W, projW, DD * HH);
    for (int l = 0; l < 2; l++) {
        cvw(msg_W1 + (size_t)l * 520 * HH,     msgW1h + (size_t)l * HH * HH, HH * HH);
        cvw(msg_W2 + (size_t)l * HH * HH,      msgW2h + (size_t)l * HH * HH, HH * HH);
        cvw(att_W1 + (size_t)l * 520 * (HH/2), attW1h + (size_t)l * HH * (HH/2), HH * (HH/2));
        cvw(att_W2 + (size_t)l * (HH/2) * HH,  attW2h + (size_t)l * (HH/2) * HH, (HH/2) * HH);
        int tot = HH * G3H;
        cvt_w_gru_k<<<(tot + 255) / 256, 256>>>(gru_Wih + (size_t)l * G3H * HH,
                                                Wihh + (size_t)l * HH * G3H);
        cvt_w_gru_k<<<(tot + 255) / 256, 256>>>(gru_Whh + (size_t)l * G3H * HH,
                                                Whhh + (size_t)l * HH * G3H);
    }
    cvw(head_W1, headW1h, HH * HH);

    // ---- text projection ----
    cvt_text_k<<<(BB * (TT / 4) + 255) / 256, 256>>>(text_ab);
    launch_hgemm(1, 1, text_e, textW, tx, nullptr, text_b, nullptr, BB, DD, TT);

    // ---- gather + input projection ----
    gather_emb_k<<<(4 * BB * (DD / 4) + 255) / 256, 256>>>(a_ids, ev_ids, b_ids, c_ids, ent);
    launch_hgemm(1, 3, emb4_e, projW, state, state_e, proj_b, nullptr, 4 * BB, HH, DD);

    const int ew = 4 * BB * (HH / 4);
    const int ed = 3 * BB * (HH / 4);

    for (int ii = 0; ii < 2; ii++) {
        if (ii) relu_state_k<<<(ew + 255) / 256, 256>>>();
        const float* mW1 = msg_W1 + (size_t)ii * 520 * HH;
        const float* aW1 = att_W1 + (size_t)ii * 520 * (HH / 2);
        for (int p = 0; p < 2; p++) {
            diff_cvt_k<<<(ed + 255) / 256, 256>>>();
            // hidm_e = relu(diff @ W1 + b1 + edgebias)
            launch_hgemm(2, 2, diff_e, msgW1h + (size_t)ii * HH * HH,
                         nullptr, hidm_e, msg_b1 + ii * HH, mW1 + 512 * HH,
                         3 * BB, HH, HH);
            // msg = hidm @ W2 + b2   (fp32)
            launch_hgemm(0, 1, hidm_e, msgW2h + (size_t)ii * HH * HH,
                         msgp, nullptr, msg_b2 + ii * HH, nullptr, 3 * BB, HH, HH);
            // hida_e = relu(diff @ attW1 + b + edgebias)
            launch_hgemm(2, 2, diff_e, attW1h + (size_t)ii * HH * (HH/2),
                         nullptr, hida_e, att_b1 + ii * (HH / 2), aW1 + 512 * (HH / 2),
                         3 * BB, HH / 2, HH);
            // msgatt_e = msg * sigmoid(hida @ attW2 + b)
            launch_hgemm(3, 2, hida_e, attW2h + (size_t)ii * (HH/2) * HH,
                         nullptr, msgatt_e, att_b2 + ii * HH, msgp, 3 * BB, HH, HH / 2);
            // gi = msgatt @ Wih^T + bih
            launch_hgemm(0, 1, msgatt_e, Wihh + (size_t)ii * HH * G3H,
                         gi, nullptr, gru_bih + ii * G3H, nullptr, 3 * BB, G3H, HH);
            // gh = state @ Whh^T + bhh
            launch_hgemm(0, 1, state_e, Whhh + (size_t)ii * HH * G3H,
                         gh, nullptr, gru_bhh + ii * G3H, nullptr, 4 * BB, G3H, HH);
            // GRU update
            gru_k<<<(ew + 255) / 256, 256>>>(gru_bih + ii * G3H);
        }
    }

    // ---- head ----
    dd_cvt_k<<<(BB * (HH / 4) + 255) / 256, 256>>>();
    launch_hgemm(1, 1, ddv_e, headW1h, hh, nullptr, head_b1, nullptr, BB, HH, HH);
    head2_k<<<BB / 8, 256>>>(head_W2, head_b2, out);
}

// round 8
// speedup vs baseline: 1.0928x; 1.0928x over previous
#include <cuda_runtime.h>
#include <cuda_fp16.h>
#include <math.h>
#include <stdint.h>
#include <stddef.h>

// Problem constants
#define BB   16384            // batch / paths
#define DD   256              // embedding dim
#define HH   512              // hidden dim
#define TT   768              // text dim
#define RR   32               // relation classes
#define G3H  1536             // 3*H

typedef __half  fp16;
typedef __half2 fp162;

// ---------------------------------------------------------------------------
// Scratch. "_e" buffers: hi/lo extended fp16 activations: logical [M,K] fp32
// stored as [M,2K]: cols [0,K)=hi, [K,2K)=lo. Weights: PLAIN fp16 [K,N].
// ---------------------------------------------------------------------------
__device__ __align__(128) float g_tx   [(size_t)BB * DD];
__device__ __align__(128) float g_state[(size_t)4 * BB * HH];
__device__ __align__(128) float g_msg  [(size_t)3 * BB * HH];
__device__ __align__(128) float g_gi   [(size_t)3 * BB * G3H];
__device__ __align__(128) float g_gh   [(size_t)4 * BB * G3H];
__device__ __align__(128) float g_hh   [(size_t)BB * HH];

__device__ __align__(128) fp16 g_text_e  [(size_t)BB * 2 * TT];
__device__ __align__(128) fp16 g_emb4_e  [(size_t)4 * BB * 2 * DD];
__device__ __align__(128) fp16 g_state_e [(size_t)4 * BB * 2 * HH];
__device__ __align__(128) fp16 g_diff_e  [(size_t)3 * BB * 2 * HH];
__device__ __align__(128) fp16 g_hidm_e  [(size_t)3 * BB * 2 * HH];
__device__ __align__(128) fp16 g_hida_e  [(size_t)3 * BB * HH];        // 2*(H/2)
__device__ __align__(128) fp16 g_msgatt_e[(size_t)3 * BB * 2 * HH];
__device__ __align__(128) fp16 g_ddv_e   [(size_t)BB * 2 * HH];

// plain fp16 weights [K,N]
__device__ __align__(128) fp16 g_textW_h [(size_t)TT * DD];
__device__ __align__(128) fp16 g_projW_h [(size_t)DD * HH];
__device__ __align__(128) fp16 g_msgW1_h [2][(size_t)HH * HH];
__device__ __align__(128) fp16 g_msgW2_h [2][(size_t)HH * HH];
__device__ __align__(128) fp16 g_attW1_h [2][(size_t)HH * (HH/2)];
__device__ __align__(128) fp16 g_attW2_h [2][(size_t)(HH/2) * HH];
__device__ __align__(128) fp16 g_Wih_h   [2][(size_t)HH * G3H];
__device__ __align__(128) fp16 g_Whh_h   [2][(size_t)HH * G3H];
__device__ __align__(128) fp16 g_headW1_h[(size_t)HH * HH];

// ---------------------------------------------------------------------------
// Small helpers
// ---------------------------------------------------------------------------
__device__ __forceinline__ uint32_t smem_u32(const void* p) {
    return (uint32_t)__cvta_generic_to_shared(p);
}
__device__ __forceinline__ void cp16c(void* s, const void* g) {
    asm volatile("cp.async.cg.shared.global [%0], [%1], 16;\n"
                 :: "r"(smem_u32(s)), "l"(g));
}
__device__ __forceinline__ void cp_commit() {
    asm volatile("cp.async.commit_group;\n");
}
__device__ __forceinline__ void cp_wait0() {
    asm volatile("cp.async.wait_group 0;\n");
}
__device__ __forceinline__ void cp_wait1() {
    asm volatile("cp.async.wait_group 1;\n");
}
#define LDSM_X4(r0,r1,r2,r3,addr) \
    asm volatile("ldmatrix.sync.aligned.m8n8.x4.shared.b16 {%0,%1,%2,%3}, [%4];" \
        : "=r"(r0),"=r"(r1),"=r"(r2),"=r"(r3) : "r"(addr))
#define LDSM_X4T(r0,r1,r2,r3,addr) \
    asm volatile("ldmatrix.sync.aligned.m8n8.x4.trans.shared.b16 {%0,%1,%2,%3}, [%4];" \
        : "=r"(r0),"=r"(r1),"=r"(r2),"=r"(r3) : "r"(addr))
__device__ __forceinline__ void mma16816(float* d, const uint32_t* a, const uint32_t* b) {
    asm volatile(
        "mma.sync.aligned.m16n8k16.row.col.f32.f16.f16.f32 "
        "{%0,%1,%2,%3},{%4,%5,%6,%7},{%8,%9},{%0,%1,%2,%3};"
        : "+f"(d[0]), "+f"(d[1]), "+f"(d[2]), "+f"(d[3])
        : "r"(a[0]), "r"(a[1]), "r"(a[2]), "r"(a[3]), "r"(b[0]), "r"(b[1]));
}

__device__ __forceinline__ float sigf(float x) { return 1.f / (1.f + expf(-x)); }

// write 4 fp32 values as hi/lo fp16 quads
__device__ __forceinline__ void hilo4(float4 v, fp16* hp, fp16* lp) {
    fp16 hx = __float2half_rn(v.x), hy = __float2half_rn(v.y);
    fp16 hz = __float2half_rn(v.z), hw = __float2half_rn(v.w);
    ((fp162*)hp)[0] = __halves2half2(hx, hy);
    ((fp162*)hp)[1] = __halves2half2(hz, hw);
    ((fp162*)lp)[0] = __halves2half2(
        __float2half_rn(v.x - __half2float(hx)),
        __float2half_rn(v.y - __half2float(hy)));
    ((fp162*)lp)[1] = __halves2half2(
        __float2half_rn(v.z - __half2float(hz)),
        __float2half_rn(v.w - __half2float(hw)));
}

// ---------------------------------------------------------------------------
// fp16 tensor-core GEMM, hi/lo compensation on A (PASSES = 2) or plain (1).
// A: [M, 2K] ext fp16, W: [K, N] plain fp16.
// EPI: 0 = +bias, 1 = relu(+bias), 2 = relu(+bias + aux[m>>14][n]),
//      3 = aux[m,n] * sigmoid(+bias)
// OUT bit0: fp32 C[m*N+n]; bit1: ext fp16 E[m*2N + (n | N+n)]
// Tile 128x128x32, 256 threads (8 warps: 4 along M x 2 along N).
// ---------------------------------------------------------------------------
template<int EPI, int OUT, int PASSES>
__global__ __launch_bounds__(256)
void hgemm_k(const fp16* __restrict__ A, const fp16* __restrict__ W,
             float* __restrict__ C, fp16* __restrict__ E,
             const float* __restrict__ bias, const float* __restrict__ aux,
             int M, int N, int K)
{
    __shared__ __align__(16) fp16 sA[2][128][40];   // 32 + 8 pad
    __shared__ __align__(16) fp16 sB[2][32][136];   // 128 + 8 pad

    const int tid = threadIdx.x;
    const int m0 = blockIdx.y * 128, n0 = blockIdx.x * 128;
    const int warp = tid >> 5, lane = tid & 31;
    const int wm = warp & 3, wn = warp >> 2;

    const int kIters = K >> 5;
    const int T = PASSES * kIters;
    const size_t lda = 2 * (size_t)K;

    float acc[2][8][4];
#pragma unroll
    for (int i = 0; i < 2; i++)
#pragma unroll
        for (int j = 0; j < 8; j++)
#pragma unroll
            for (int q = 0; q < 4; q++) acc[i][j][q] = 0.f;

    const int arow = tid >> 1, acc0 = (tid & 1) * 16;
    const int brow = tid >> 3, bcc0 = (tid & 7) * 16;

    auto load_tile = [&](int it, int buf) {
        int p  = it / kIters;                 // 0: hi, 1: lo
        int kb = it - p * kIters;
        int k0 = kb << 5;
        int aoff = (p == 1) ? K : 0;
        const fp16* ga = A + (size_t)(m0 + arow) * lda + aoff + k0 + acc0;
        cp16c(&sA[buf][arow][acc0],     ga);
        cp16c(&sA[buf][arow][acc0 + 8], ga + 8);
        const fp16* gb = W + (size_t)(k0 + brow) * N + n0 + bcc0;
        cp16c(&sB[buf][brow][bcc0],     gb);
        cp16c(&sB[buf][brow][bcc0 + 8], gb + 8);
        cp_commit();
    };

    load_tile(0, 0);

    for (int it = 0; it < T; ++it) {
        const int buf = it & 1;
        if (it + 1 < T) { load_tile(it + 1, buf ^ 1); cp_wait1(); }
        else            { cp_wait0(); }
        __syncthreads();

#pragma unroll
        for (int kk = 0; kk < 2; ++kk) {
            uint32_t afrag[2][4];
#pragma unroll
            for (int mt = 0; mt < 2; ++mt) {
                int r = wm * 32 + mt * 16 + (lane & 15);
                int c = kk * 16 + ((lane >> 4) << 3);
                LDSM_X4(afrag[mt][0], afrag[mt][1], afrag[mt][2], afrag[mt][3],
                        smem_u32(&sA[buf][r][c]));
            }
            uint32_t bfrag[8][2];
#pragma unroll
            for (int tp = 0; tp < 4; ++tp) {
                int g = lane >> 3, lr = lane & 7;
                int row = kk * 16 + ((g & 1) << 3) + lr;
                int col = wn * 64 + tp * 16 + ((g >> 1) << 3);
                uint32_t r0, r1, r2, r3;
                LDSM_X4T(r0, r1, r2, r3, smem_u32(&sB[buf][row][col]));
                bfrag[tp * 2][0] = r0;     bfrag[tp * 2][1] = r1;
                bfrag[tp * 2 + 1][0] = r2; bfrag[tp * 2 + 1][1] = r3;
            }
#pragma unroll
            for (int mt = 0; mt < 2; ++mt)
#pragma unroll
                for (int nt = 0; nt < 8; ++nt)
                    mma16816(acc[mt][nt], afrag[mt], bfrag[nt]);
        }
        __syncthreads();
    }

    // epilogue
    const int r0 = lane >> 2, c0 = (lane & 3) * 2;
#pragma unroll
    for (int mt = 0; mt < 2; ++mt) {
#pragma unroll
        for (int half = 0; half < 2; ++half) {
            const int m = m0 + wm * 32 + mt * 16 + r0 + half * 8;
            const int et = m >> 14;
#pragma unroll
            for (int nt = 0; nt < 8; ++nt) {
                const int n = n0 + wn * 64 + nt * 8 + c0;
                float v0 = acc[mt][nt][half * 2 + 0] + bias[n];
                float v1 = acc[mt][nt][half * 2 + 1] + bias[n + 1];
                if (EPI == 2) {
                    v0 += aux[(size_t)et * N + n];
                    v1 += aux[(size_t)et * N + n + 1];
                }
                if (EPI == 1 || EPI == 2) { v0 = fmaxf(v0, 0.f); v1 = fmaxf(v1, 0.f); }
                if (EPI == 3) {
                    v0 = aux[(size_t)m * N + n]     * sigf(v0);
                    v1 = aux[(size_t)m * N + n + 1] * sigf(v1);
                }
                if (OUT & 1) {
                    float2 fv = {v0, v1};
                    *(float2*)&C[(size_t)m * N + n] = fv;
                }
                if (OUT & 2) {
                    fp16 h0 = __float2half_rn(v0), h1 = __float2half_rn(v1);
                    fp16* base = E + (size_t)m * 2 * N;
                    *(fp162*)(base + n) = __halves2half2(h0, h1);
                    *(fp162*)(base + N + n) = __halves2half2(
                        __float2half_rn(v0 - __half2float(h0)),
                        __float2half_rn(v1 - __half2float(h1)));
                }
            }
        }
    }
}

// ---------------------------------------------------------------------------
// Conversion / elementwise kernels
// ---------------------------------------------------------------------------

// fp32 W[K,N] -> plain fp16 [K,N]
__global__ void cvt_w_k(const float* __restrict__ W, fp16* __restrict__ E, int KN)
{
    int gid = blockIdx.x * blockDim.x + threadIdx.x;
    if (gid * 4 >= KN) return;
    float4 v = *(const float4*)(W + (size_t)gid * 4);
    fp16* p = E + (size_t)gid * 4;
    ((fp162*)p)[0] = __halves2half2(__float2half_rn(v.x), __float2half_rn(v.y));
    ((fp162*)p)[1] = __halves2half2(__float2half_rn(v.z), __float2half_rn(v.w));
}

// GRU weight (3H,H) row-major -> transposed plain fp16 [H, 3H]
__global__ void cvt_w_gru_k(const float* __restrict__ Wg, fp16* __restrict__ E)
{
    int gid = blockIdx.x * blockDim.x + threadIdx.x;     // over H*3H
    if (gid >= HH * G3H) return;
    int k = gid / G3H, j = gid - k * G3H;
    E[gid] = __float2half_rn(Wg[(size_t)j * HH + k]);
}

// text_ab fp32 [B,T] -> ext [B,2T]
__global__ void cvt_text_k(const float* __restrict__ X)
{
    int gid = blockIdx.x * blockDim.x + threadIdx.x;     // B * T/4
    if (gid >= BB * (TT / 4)) return;
    int m = gid / (TT / 4), q = gid - m * (TT / 4);
    float4 v = *(const float4*)(X + (size_t)m * TT + q * 4);
    fp16* base = g_text_e + (size_t)m * 2 * TT;
    hilo4(v, base + q * 4, base + TT + q * 4);
}

// gather node embeddings (event gets +tx) -> ext [4B, 2D]
__global__ void gather_emb_k(const int* __restrict__ a, const int* __restrict__ ev,
                             const int* __restrict__ b, const int* __restrict__ c,
                             const float* __restrict__ ent)
{
    int gid = blockIdx.x * blockDim.x + threadIdx.x;     // 4B * 64
    if (gid >= 4 * BB * (DD / 4)) return;
    int row = gid >> 6, c4 = (gid & 63) * 4;
    int sel = row >> 14, r = row & (BB - 1);
    int id = (sel == 0) ? a[r] : (sel == 1) ? ev[r] : (sel == 2) ? b[r] : c[r];
    float4 v = *(const float4*)(ent + (size_t)id * DD + c4);
    if (sel == 1) {
        float4 tv = *(const float4*)(g_tx + (size_t)r * DD + c4);
        v.x += tv.x; v.y += tv.y; v.z += tv.z; v.w += tv.w;
    }
    fp16* base = g_emb4_e + (size_t)row * 2 * DD;
    hilo4(v, base + c4, base + DD + c4);
}

// diff = state[src] - state[dst] -> ext [3B, 2H]
__global__ void diff_cvt_k()
{
    int gid = blockIdx.x * blockDim.x + threadIdx.x;     // 3B * 128
    if (gid >= 3 * BB * (HH / 4)) return;
    int row = gid >> 7, c = (gid & 127) * 4;
    int src = (row < 2 * BB) ? row : row - BB;
    float4 s = *(const float4*)(g_state + (size_t)src * HH + c);
    float4 d = *(const float4*)(g_state + (size_t)(row + BB) * HH + c);
    s.x -= d.x; s.y -= d.y; s.z -= d.z; s.w -= d.w;
    fp16* base = g_diff_e + (size_t)row * 2 * HH;
    hilo4(s, base + c, base + HH + c);
}

// state = relu(state), refresh ext
__global__ void relu_state_k()
{
    int gid = blockIdx.x * blockDim.x + threadIdx.x;     // 4B * 128
    if (gid >= 4 * BB * (HH / 4)) return;
    int row = gid >> 7, c = (gid & 127) * 4;
    float4 v = *(float4*)(g_state + (size_t)row * HH + c);
    v.x = fmaxf(v.x, 0.f); v.y = fmaxf(v.y, 0.f);
    v.z = fmaxf(v.z, 0.f); v.w = fmaxf(v.w, 0.f);
    *(float4*)(g_state + (size_t)row * HH + c) = v;
    fp16* base = g_state_e + (size_t)row * 2 * HH;
    hilo4(v, base + c, base + HH + c);
}

// GRU elementwise update; writes state fp32 + ext
__global__ void gru_k(const float* __restrict__ bih)
{
    int gid = blockIdx.x * blockDim.x + threadIdx.x;     // 4B * 128
    if (gid >= 4 * BB * (HH / 4)) return;
    int m = gid >> 7, c = (gid & 127) * 4;

    const float* ghr = g_gh + (size_t)m * G3H;
    float4 hr = *(const float4*)(ghr + c);
    float4 hz = *(const float4*)(ghr + HH + c);
    float4 hn = *(const float4*)(ghr + 2 * HH + c);

    float4 ir, iz, in_;
    if (m < BB) {
        ir  = *(const float4*)(bih + c);
        iz  = *(const float4*)(bih + HH + c);
        in_ = *(const float4*)(bih + 2 * HH + c);
    } else {
        const float* gir = g_gi + (size_t)(m - BB) * G3H;
        ir  = *(const float4*)(gir + c);
        iz  = *(const float4*)(gir + HH + c);
        in_ = *(const float4*)(gir + 2 * HH + c);
    }
    float4 old = *(const float4*)(g_state + (size_t)m * HH + c);

    float4 out;
    { float r = sigf(ir.x + hr.x), z = sigf(iz.x + hz.x);
      float n = tanhf(in_.x + r * hn.x); out.x = (1.f - z) * n + z * old.x; }
    { float r = sigf(ir.y + hr.y), z = sigf(iz.y + hz.y);
      float n = tanhf(in_.y + r * hn.y); out.y = (1.f - z) * n + z * old.y; }
    { float r = sigf(ir.z + hr.z), z = sigf(iz.z + hz.z);
      float n = tanhf(in_.z + r * hn.z); out.z = (1.f - z) * n + z * old.z; }
    { float r = sigf(ir.w + hr.w), z = sigf(iz.w + hz.w);
      float n = tanhf(in_.w + r * hn.w); out.w = (1.f - z) * n + z * old.w; }

    *(float4*)(g_state + (size_t)m * HH + c) = out;
    fp16* base = g_state_e + (size_t)m * 2 * HH;
    hilo4(out, base + c, base + HH + c);
}

// head diff -> ext [B, 2H]
__global__ void dd_cvt_k()
{
    int gid = blockIdx.x * blockDim.x + threadIdx.x;     // B * 128
    if (gid >= BB * (HH / 4)) return;
    int row = gid >> 7, c = (gid & 127) * 4;
    float4 a = *(const float4*)(g_state + (size_t)row * HH + c);
    float4 b = *(const float4*)(g_state + (size_t)(row + 2 * BB) * HH + c);
    a.x -= b.x; a.y -= b.y; a.z -= b.z; a.w -= b.w;
    fp16* base = g_ddv_e + (size_t)row * 2 * HH;
    hilo4(a, base + c, base + HH + c);
}

// final head: out[B,32] = hh[B,512] @ W2[512,32] + b2 (fp32, tiny)
__global__ void head2_k(const float* __restrict__ W2, const float* __restrict__ b2,
                        float* __restrict__ out)
{
    int r = threadIdx.x >> 5, col = threadIdx.x & 31;
    int row = blockIdx.x * 8 + r;
    const float* h = g_hh + (size_t)row * HH;
    float acc = b2[col];
#pragma unroll 8
    for (int k = 0; k < HH; k++)
        acc = fmaf(h[k], W2[k * RR + col], acc);
    out[(size_t)row * RR + col] = acc;
}

// ---------------------------------------------------------------------------
// Host launch
// ---------------------------------------------------------------------------
template<int EPI, int OUT, int PASSES>
static void rg(const fp16* A, const fp16* W, float* C, fp16* E,
               const float* bias, const float* aux, int M, int N, int K)
{
    dim3 grid(N / 128, M / 128);
    hgemm_k<EPI, OUT, PASSES><<<grid, 256>>>(A, W, C, E, bias, aux, M, N, K);
}

extern "C" void kernel_launch(void* const* d_in, const int* in_sizes, int n_in,
                              void* d_out, int out_size)
{
    const int*   a_ids   = (const int*)  d_in[0];
    const int*   ev_ids  = (const int*)  d_in[1];
    const int*   b_ids   = (const int*)  d_in[2];
    const int*   c_ids   = (const int*)  d_in[3];
    const float* text_ab = (const float*)d_in[4];
    const float* ent     = (const float*)d_in[5];
    const float* text_W  = (const float*)d_in[6];
    const float* text_b  = (const float*)d_in[7];
    const float* proj_W  = (const float*)d_in[8];
    const float* proj_b  = (const float*)d_in[9];
    const float* msg_W1  = (const float*)d_in[10];
    const float* msg_b1  = (const float*)d_in[11];
    const float* msg_W2  = (const float*)d_in[12];
    const float* msg_b2  = (const float*)d_in[13];
    const float* att_W1  = (const float*)d_in[14];
    const float* att_b1  = (const float*)d_in[15];
    const float* att_W2  = (const float*)d_in[16];
    const float* att_b2  = (const float*)d_in[17];
    const float* gru_Wih = (const float*)d_in[18];
    const float* gru_Whh = (const float*)d_in[19];
    const float* gru_bih = (const float*)d_in[20];
    const float* gru_bhh = (const float*)d_in[21];
    const float* head_W1 = (const float*)d_in[22];
    const float* head_b1 = (const float*)d_in[23];
    const float* head_W2 = (const float*)d_in[24];
    const float* head_b2 = (const float*)d_in[25];
    float* out = (float*)d_out;

    float *tx, *state, *msgp, *gi, *gh, *hh;
    fp16 *text_e, *emb4_e, *state_e, *diff_e, *hidm_e, *hida_e, *msgatt_e, *ddv_e;
    fp16 *textW, *projW, *msgW1h, *msgW2h, *attW1h, *attW2h, *Wihh, *Whhh, *headW1h;
    cudaGetSymbolAddress((void**)&tx,       g_tx);
    cudaGetSymbolAddress((void**)&state,    g_state);
    cudaGetSymbolAddress((void**)&msgp,     g_msg);
    cudaGetSymbolAddress((void**)&gi,       g_gi);
    cudaGetSymbolAddress((void**)&gh,       g_gh);
    cudaGetSymbolAddress((void**)&hh,       g_hh);
    cudaGetSymbolAddress((void**)&text_e,   g_text_e);
    cudaGetSymbolAddress((void**)&emb4_e,   g_emb4_e);
    cudaGetSymbolAddress((void**)&state_e,  g_state_e);
    cudaGetSymbolAddress((void**)&diff_e,   g_diff_e);
    cudaGetSymbolAddress((void**)&hidm_e,   g_hidm_e);
    cudaGetSymbolAddress((void**)&hida_e,   g_hida_e);
    cudaGetSymbolAddress((void**)&msgatt_e, g_msgatt_e);
    cudaGetSymbolAddress((void**)&ddv_e,    g_ddv_e);
    cudaGetSymbolAddress((void**)&textW,    g_textW_h);
    cudaGetSymbolAddress((void**)&projW,    g_projW_h);
    cudaGetSymbolAddress((void**)&msgW1h,   g_msgW1_h);
    cudaGetSymbolAddress((void**)&msgW2h,   g_msgW2_h);
    cudaGetSymbolAddress((void**)&attW1h,   g_attW1_h);
    cudaGetSymbolAddress((void**)&attW2h,   g_attW2_h);
    cudaGetSymbolAddress((void**)&Wihh,     g_Wih_h);
    cudaGetSymbolAddress((void**)&Whhh,     g_Whh_h);
    cudaGetSymbolAddress((void**)&headW1h,  g_headW1_h);

    auto cvw = [](const float* W, fp16* E, int KN) {
        cvt_w_k<<<(KN / 4 + 255) / 256, 256>>>(W, E, KN);
    };

    // Launch order puts a big GEMM at launch index 5 so ncu (-s 5 -c 1)
    // finally captures a GEMM instead of a conversion kernel.
    cvw(text_W, textW, TT * DD);                                          // 0
    cvt_text_k<<<(BB * (TT / 4) + 255) / 256, 256>>>(text_ab);            // 1
    rg<1, 1, 1>(text_e, textW, tx, nullptr, text_b, nullptr, BB, DD, TT); // 2 (1-pass)
    cvw(proj_W, projW, DD * HH);                                          // 3
    gather_emb_k<<<(4 * BB * (DD / 4) + 255) / 256, 256>>>(a_ids, ev_ids, b_ids, c_ids, ent); // 4
    rg<1, 3, 2>(emb4_e, projW, state, state_e, proj_b, nullptr, 4 * BB, HH, DD);              // 5 <- profiled

    // remaining weight conversions
    for (int l = 0; l < 2; l++) {
        cvw(msg_W1 + (size_t)l * 520 * HH,     msgW1h + (size_t)l * HH * HH, HH * HH);
        cvw(msg_W2 + (size_t)l * HH * HH,      msgW2h + (size_t)l * HH * HH, HH * HH);
        cvw(att_W1 + (size_t)l * 520 * (HH/2), attW1h + (size_t)l * HH * (HH/2), HH * (HH/2));
        cvw(att_W2 + (size_t)l * (HH/2) * HH,  attW2h + (size_t)l * (HH/2) * HH, (HH/2) * HH);
        int tot = HH * G3H;
        cvt_w_gru_k<<<(tot + 255) / 256, 256>>>(gru_Wih + (size_t)l * G3H * HH,
                                                Wihh + (size_t)l * HH * G3H);
        cvt_w_gru_k<<<(tot + 255) / 256, 256>>>(gru_Whh + (size_t)l * G3H * HH,
                                                Whhh + (size_t)l * HH * G3H);
    }
    cvw(head_W1, headW1h, HH * HH);

    const int ew = 4 * BB * (HH / 4);
    const int ed = 3 * BB * (HH / 4);

    for (int ii = 0; ii < 2; ii++) {
        if (ii) relu_state_k<<<(ew + 255) / 256, 256>>>();
        const float* mW1 = msg_W1 + (size_t)ii * 520 * HH;
        const float* aW1 = att_W1 + (size_t)ii * 520 * (HH / 2);
        for (int p = 0; p < 2; p++) {
            diff_cvt_k<<<(ed + 255) / 256, 256>>>();
            // hidm_e = relu(diff @ W1 + b1 + edgebias)          [2-pass]
            rg<2, 2, 2>(diff_e, msgW1h + (size_t)ii * HH * HH,
                        nullptr, hidm_e, msg_b1 + ii * HH, mW1 + 512 * HH,
                        3 * BB, HH, HH);
            // msg = hidm @ W2 + b2 (fp32)                        [2-pass]
            rg<0, 1, 2>(hidm_e, msgW2h + (size_t)ii * HH * HH,
                        msgp, nullptr, msg_b2 + ii * HH, nullptr, 3 * BB, HH, HH);
            // hida_e = relu(diff @ attW1 + b + edgebias)         [1-pass]
            rg<2, 2, 1>(diff_e, attW1h + (size_t)ii * HH * (HH/2),
                        nullptr, hida_e, att_b1 + ii * (HH / 2), aW1 + 512 * (HH / 2),
                        3 * BB, HH / 2, HH);
            // msgatt_e = msg * sigmoid(hida @ attW2 + b)         [1-pass]
            rg<3, 2, 1>(hida_e, attW2h + (size_t)ii * (HH/2) * HH,
                        nullptr, msgatt_e, att_b2 + ii * HH, msgp, 3 * BB, HH, HH / 2);
            // gi = msgatt @ Wih^T + bih                          [2-pass]
            rg<0, 1, 2>(msgatt_e, Wihh + (size_t)ii * HH * G3H,
                        gi, nullptr, gru_bih + ii * G3H, nullptr, 3 * BB, G3H, HH);
            // gh = state @ Whh^T + bhh                           [2-pass]
            rg<0, 1, 2>(state_e, Whhh + (size_t)ii * HH * G3H,
                        gh, nullptr, gru_bhh + ii * G3H, nullptr, 4 * BB, G3H, HH);
            // GRU update
            gru_k<<<(ew + 255) / 256, 256>>>(gru_bih + ii * G3H);
        }
    }

    // ---- head ----
    dd_cvt_k<<<(BB * (HH / 4) + 255) / 256, 256>>>();
    rg<1, 1, 2>(ddv_e, headW1h, hh, nullptr, head_b1, nullptr, BB, HH, HH);
    head2_k<<<BB / 8, 256>>>(head_W2, head_b2, out);
}

// round 9
// speedup vs baseline: 1.5284x; 1.3986x over previous
#include <cuda_runtime.h>
#include <cuda_fp16.h>
#include <math.h>
#include <stdint.h>
#include <stddef.h>

// Problem constants
#define BB   16384            // batch / paths
#define DD   256              // embedding dim
#define HH   512              // hidden dim
#define TT   768              // text dim
#define RR   32               // relation classes
#define G3H  1536             // 3*H

typedef __half  fp16;
typedef __half2 fp162;

// ---------------------------------------------------------------------------
// Scratch. "_e" buffers: hi/lo extended fp16 activations: logical [M,K] fp32
// stored as [M,2K]: cols [0,K)=hi, [K,2K)=lo. Weights: PLAIN fp16 [K,N].
// ---------------------------------------------------------------------------
__device__ __align__(128) float g_tx   [(size_t)BB * DD];
__device__ __align__(128) float g_state[(size_t)4 * BB * HH];
__device__ __align__(128) float g_msg  [(size_t)3 * BB * HH];
__device__ __align__(128) float g_gi   [(size_t)3 * BB * G3H];
__device__ __align__(128) float g_gh   [(size_t)4 * BB * G3H];
__device__ __align__(128) float g_hh   [(size_t)BB * HH];

__device__ __align__(128) fp16 g_text_e  [(size_t)BB * 2 * TT];
__device__ __align__(128) fp16 g_emb4_e  [(size_t)4 * BB * 2 * DD];
__device__ __align__(128) fp16 g_state_e [(size_t)4 * BB * 2 * HH];
__device__ __align__(128) fp16 g_diff_e  [(size_t)3 * BB * 2 * HH];
__device__ __align__(128) fp16 g_hidm_e  [(size_t)3 * BB * 2 * HH];
__device__ __align__(128) fp16 g_hida_e  [(size_t)3 * BB * HH];        // 2*(H/2)
__device__ __align__(128) fp16 g_msgatt_e[(size_t)3 * BB * 2 * HH];
__device__ __align__(128) fp16 g_ddv_e   [(size_t)BB * 2 * HH];

// plain fp16 weights [K,N]
__device__ __align__(128) fp16 g_textW_h [(size_t)TT * DD];
__device__ __align__(128) fp16 g_projW_h [(size_t)DD * HH];
__device__ __align__(128) fp16 g_msgW1_h [2][(size_t)HH * HH];
__device__ __align__(128) fp16 g_msgW2_h [2][(size_t)HH * HH];
__device__ __align__(128) fp16 g_attW1_h [2][(size_t)HH * (HH/2)];
__device__ __align__(128) fp16 g_attW2_h [2][(size_t)(HH/2) * HH];
__device__ __align__(128) fp16 g_Wih_h   [2][(size_t)HH * G3H];
__device__ __align__(128) fp16 g_Whh_h   [2][(size_t)HH * G3H];
__device__ __align__(128) fp16 g_headW1_h[(size_t)HH * HH];

// ---------------------------------------------------------------------------
// Small helpers
// ---------------------------------------------------------------------------
__device__ __forceinline__ uint32_t smem_u32(const void* p) {
    return (uint32_t)__cvta_generic_to_shared(p);
}
__device__ __forceinline__ void cp16c(void* s, const void* g) {
    asm volatile("cp.async.cg.shared.global [%0], [%1], 16;\n"
                 :: "r"(smem_u32(s)), "l"(g));
}
__device__ __forceinline__ void cp_commit() {
    asm volatile("cp.async.commit_group;\n");
}
__device__ __forceinline__ void cp_wait0() {
    asm volatile("cp.async.wait_group 0;\n");
}
__device__ __forceinline__ void cp_wait1() {
    asm volatile("cp.async.wait_group 1;\n");
}
#define LDSM_X4(r0,r1,r2,r3,addr) \
    asm volatile("ldmatrix.sync.aligned.m8n8.x4.shared.b16 {%0,%1,%2,%3}, [%4];" \
        : "=r"(r0),"=r"(r1),"=r"(r2),"=r"(r3) : "r"(addr))
#define LDSM_X4T(r0,r1,r2,r3,addr) \
    asm volatile("ldmatrix.sync.aligned.m8n8.x4.trans.shared.b16 {%0,%1,%2,%3}, [%4];" \
        : "=r"(r0),"=r"(r1),"=r"(r2),"=r"(r3) : "r"(addr))
__device__ __forceinline__ void mma16816(float* d, const uint32_t* a, const uint32_t* b) {
    asm volatile(
        "mma.sync.aligned.m16n8k16.row.col.f32.f16.f16.f32 "
        "{%0,%1,%2,%3},{%4,%5,%6,%7},{%8,%9},{%0,%1,%2,%3};"
        : "+f"(d[0]), "+f"(d[1]), "+f"(d[2]), "+f"(d[3])
        : "r"(a[0]), "r"(a[1]), "r"(a[2]), "r"(a[3]), "r"(b[0]), "r"(b[1]));
}

__device__ __forceinline__ float sigf(float x) { return 1.f / (1.f + expf(-x)); }

// write 4 fp32 values as hi/lo fp16 quads
__device__ __forceinline__ void hilo4(float4 v, fp16* hp, fp16* lp) {
    fp16 hx = __float2half_rn(v.x), hy = __float2half_rn(v.y);
    fp16 hz = __float2half_rn(v.z), hw = __float2half_rn(v.w);
    ((fp162*)hp)[0] = __halves2half2(hx, hy);
    ((fp162*)hp)[1] = __halves2half2(hz, hw);
    ((fp162*)lp)[0] = __halves2half2(
        __float2half_rn(v.x - __half2float(hx)),
        __float2half_rn(v.y - __half2float(hy)));
    ((fp162*)lp)[1] = __halves2half2(
        __float2half_rn(v.z - __half2float(hz)),
        __float2half_rn(v.w - __half2float(hw)));
}

// ---------------------------------------------------------------------------
// fp16 tensor-core GEMM, hi/lo compensation on A (PASSES = 2) or plain (1).
// A: [M, 2K] ext fp16, W: [K, N] plain fp16.
// EPI: 0 = +bias, 1 = relu(+bias), 2 = relu(+bias + aux[m>>14][n]),
//      3 = aux[m,n] * sigmoid(+bias)
// OUT bit0: fp32 C[m*N+n]; bit1: ext fp16 E[m*2N + (n | N+n)]
// Tile 128x128x32, 256 threads (8 warps: 4 along M x 2 along N).
// ---------------------------------------------------------------------------
template<int EPI, int OUT, int PASSES>
__global__ __launch_bounds__(256)
void hgemm_k(const fp16* __restrict__ A, const fp16* __restrict__ W,
             float* __restrict__ C, fp16* __restrict__ E,
             const float* __restrict__ bias, const float* __restrict__ aux,
             int M, int N, int K)
{
    __shared__ __align__(16) fp16 sA[2][128][40];   // 32 + 8 pad
    __shared__ __align__(16) fp16 sB[2][32][136];   // 128 + 8 pad

    const int tid = threadIdx.x;
    const int m0 = blockIdx.y * 128, n0 = blockIdx.x * 128;
    const int warp = tid >> 5, lane = tid & 31;
    const int wm = warp & 3, wn = warp >> 2;

    const int kIters = K >> 5;
    const int T = PASSES * kIters;
    const size_t lda = 2 * (size_t)K;

    float acc[2][8][4];
#pragma unroll
    for (int i = 0; i < 2; i++)
#pragma unroll
        for (int j = 0; j < 8; j++)
#pragma unroll
            for (int q = 0; q < 4; q++) acc[i][j][q] = 0.f;

    const int arow = tid >> 1, acc0 = (tid & 1) * 16;
    const int brow = tid >> 3, bcc0 = (tid & 7) * 16;

    auto load_tile = [&](int it, int buf) {
        int p  = it / kIters;                 // 0: hi, 1: lo
        int kb = it - p * kIters;
        int k0 = kb << 5;
        int aoff = (p == 1) ? K : 0;
        const fp16* ga = A + (size_t)(m0 + arow) * lda + aoff + k0 + acc0;
        cp16c(&sA[buf][arow][acc0],     ga);
        cp16c(&sA[buf][arow][acc0 + 8], ga + 8);
        const fp16* gb = W + (size_t)(k0 + brow) * N + n0 + bcc0;
        cp16c(&sB[buf][brow][bcc0],     gb);
        cp16c(&sB[buf][brow][bcc0 + 8], gb + 8);
        cp_commit();
    };

    load_tile(0, 0);

    for (int it = 0; it < T; ++it) {
        const int buf = it & 1;
        if (it + 1 < T) { load_tile(it + 1, buf ^ 1); cp_wait1(); }
        else            { cp_wait0(); }
        __syncthreads();

#pragma unroll
        for (int kk = 0; kk < 2; ++kk) {
            uint32_t afrag[2][4];
#pragma unroll
            for (int mt = 0; mt < 2; ++mt) {
                int r = wm * 32 + mt * 16 + (lane & 15);
                int c = kk * 16 + ((lane >> 4) << 3);
                LDSM_X4(afrag[mt][0], afrag[mt][1], afrag[mt][2], afrag[mt][3],
                        smem_u32(&sA[buf][r][c]));
            }
            uint32_t bfrag[8][2];
#pragma unroll
            for (int tp = 0; tp < 4; ++tp) {
                int g = lane >> 3, lr = lane & 7;
                int row = kk * 16 + ((g & 1) << 3) + lr;
                int col = wn * 64 + tp * 16 + ((g >> 1) << 3);
                uint32_t r0, r1, r2, r3;
                LDSM_X4T(r0, r1, r2, r3, smem_u32(&sB[buf][row][col]));
                bfrag[tp * 2][0] = r0;     bfrag[tp * 2][1] = r1;
                bfrag[tp * 2 + 1][0] = r2; bfrag[tp * 2 + 1][1] = r3;
            }
#pragma unroll
            for (int mt = 0; mt < 2; ++mt)
#pragma unroll
                for (int nt = 0; nt < 8; ++nt)
                    mma16816(acc[mt][nt], afrag[mt], bfrag[nt]);
        }
        __syncthreads();
    }

    // epilogue
    const int r0 = lane >> 2, c0 = (lane & 3) * 2;
#pragma unroll
    for (int mt = 0; mt < 2; ++mt) {
#pragma unroll
        for (int half = 0; half < 2; ++half) {
            const int m = m0 + wm * 32 + mt * 16 + r0 + half * 8;
            const int et = m >> 14;
#pragma unroll
            for (int nt = 0; nt < 8; ++nt) {
                const int n = n0 + wn * 64 + nt * 8 + c0;
                float v0 = acc[mt][nt][half * 2 + 0] + bias[n];
                float v1 = acc[mt][nt][half * 2 + 1] + bias[n + 1];
                if (EPI == 2) {
                    v0 += aux[(size_t)et * N + n];
                    v1 += aux[(size_t)et * N + n + 1];
                }
                if (EPI == 1 || EPI == 2) { v0 = fmaxf(v0, 0.f); v1 = fmaxf(v1, 0.f); }
                if (EPI == 3) {
                    v0 = aux[(size_t)m * N + n]     * sigf(v0);
                    v1 = aux[(size_t)m * N + n + 1] * sigf(v1);
                }
                if (OUT & 1) {
                    float2 fv = {v0, v1};
                    *(float2*)&C[(size_t)m * N + n] = fv;
                }
                if (OUT & 2) {
                    fp16 h0 = __float2half_rn(v0), h1 = __float2half_rn(v1);
                    fp16* base = E + (size_t)m * 2 * N;
                    *(fp162*)(base + n) = __halves2half2(h0, h1);
                    *(fp162*)(base + N + n) = __halves2half2(
                        __float2half_rn(v0 - __half2float(h0)),
                        __float2half_rn(v1 - __half2float(h1)));
                }
            }
        }
    }
}

// ---------------------------------------------------------------------------
// Conversion / elementwise kernels
// ---------------------------------------------------------------------------

// fp32 W[K,N] -> plain fp16 [K,N]
__global__ void cvt_w_k(const float* __restrict__ W, fp16* __restrict__ E, int KN)
{
    int gid = blockIdx.x * blockDim.x + threadIdx.x;
    if (gid * 4 >= KN) return;
    float4 v = *(const float4*)(W + (size_t)gid * 4);
    fp16* p = E + (size_t)gid * 4;
    ((fp162*)p)[0] = __halves2half2(__float2half_rn(v.x), __float2half_rn(v.y));
    ((fp162*)p)[1] = __halves2half2(__float2half_rn(v.z), __float2half_rn(v.w));
}

// GRU weight (3H,H) row-major -> transposed plain fp16 [H, 3H]
__global__ void cvt_w_gru_k(const float* __restrict__ Wg, fp16* __restrict__ E)
{
    int gid = blockIdx.x * blockDim.x + threadIdx.x;     // over H*3H
    if (gid >= HH * G3H) return;
    int k = gid / G3H, j = gid - k * G3H;
    E[gid] = __float2half_rn(Wg[(size_t)j * HH + k]);
}

// text_ab fp32 [B,T] -> ext [B,2T]
__global__ void cvt_text_k(const float* __restrict__ X)
{
    int gid = blockIdx.x * blockDim.x + threadIdx.x;     // B * T/4
    if (gid >= BB * (TT / 4)) return;
    int m = gid / (TT / 4), q = gid - m * (TT / 4);
    float4 v = *(const float4*)(X + (size_t)m * TT + q * 4);
    fp16* base = g_text_e + (size_t)m * 2 * TT;
    hilo4(v, base + q * 4, base + TT + q * 4);
}

// gather node embeddings (event gets +tx) -> ext [4B, 2D]
__global__ void gather_emb_k(const int* __restrict__ a, const int* __restrict__ ev,
                             const int* __restrict__ b, const int* __restrict__ c,
                             const float* __restrict__ ent)
{
    int gid = blockIdx.x * blockDim.x + threadIdx.x;     // 4B * 64
    if (gid >= 4 * BB * (DD / 4)) return;
    int row = gid >> 6, c4 = (gid & 63) * 4;
    int sel = row >> 14, r = row & (BB - 1);
    int id = (sel == 0) ? a[r] : (sel == 1) ? ev[r] : (sel == 2) ? b[r] : c[r];
    float4 v = *(const float4*)(ent + (size_t)id * DD + c4);
    if (sel == 1) {
        float4 tv = *(const float4*)(g_tx + (size_t)r * DD + c4);
        v.x += tv.x; v.y += tv.y; v.z += tv.z; v.w += tv.w;
    }
    fp16* base = g_emb4_e + (size_t)row * 2 * DD;
    hilo4(v, base + c4, base + DD + c4);
}

// diff = state[src] - state[dst] -> ext [3B, 2H]
__global__ void diff_cvt_k()
{
    int gid = blockIdx.x * blockDim.x + threadIdx.x;     // 3B * 128
    if (gid >= 3 * BB * (HH / 4)) return;
    int row = gid >> 7, c = (gid & 127) * 4;
    int src = (row < 2 * BB) ? row : row - BB;
    float4 s = *(const float4*)(g_state + (size_t)src * HH + c);
    float4 d = *(const float4*)(g_state + (size_t)(row + BB) * HH + c);
    s.x -= d.x; s.y -= d.y; s.z -= d.z; s.w -= d.w;
    fp16* base = g_diff_e + (size_t)row * 2 * HH;
    hilo4(s, base + c, base + HH + c);
}

// state = relu(state), refresh ext
__global__ void relu_state_k()
{
    int gid = blockIdx.x * blockDim.x + threadIdx.x;     // 4B * 128
    if (gid >= 4 * BB * (HH / 4)) return;
    int row = gid >> 7, c = (gid & 127) * 4;
    float4 v = *(float4*)(g_state + (size_t)row * HH + c);
    v.x = fmaxf(v.x, 0.f); v.y = fmaxf(v.y, 0.f);
    v.z = fmaxf(v.z, 0.f); v.w = fmaxf(v.w, 0.f);
    *(float4*)(g_state + (size_t)row * HH + c) = v;
    fp16* base = g_state_e + (size_t)row * 2 * HH;
    hilo4(v, base + c, base + HH + c);
}

// GRU elementwise update; writes state fp32 + ext
__global__ void gru_k(const float* __restrict__ bih)
{
    int gid = blockIdx.x * blockDim.x + threadIdx.x;     // 4B * 128
    if (gid >= 4 * BB * (HH / 4)) return;
    int m = gid >> 7, c = (gid & 127) * 4;

    const float* ghr = g_gh + (size_t)m * G3H;
    float4 hr = *(const float4*)(ghr + c);
    float4 hz = *(const float4*)(ghr + HH + c);
    float4 hn = *(const float4*)(ghr + 2 * HH + c);

    float4 ir, iz, in_;
    if (m < BB) {
        ir  = *(const float4*)(bih + c);
        iz  = *(const float4*)(bih + HH + c);
        in_ = *(const float4*)(bih + 2 * HH + c);
    } else {
        const float* gir = g_gi + (size_t)(m - BB) * G3H;
        ir  = *(const float4*)(gir + c);
        iz  = *(const float4*)(gir + HH + c);
        in_ = *(const float4*)(gir + 2 * HH + c);
    }
    float4 old = *(const float4*)(g_state + (size_t)m * HH + c);

    float4 out;
    { float r = sigf(ir.x + hr.x), z = sigf(iz.x + hz.x);
      float n = tanhf(in_.x + r * hn.x); out.x = (1.f - z) * n + z * old.x; }
    { float r = sigf(ir.y + hr.y), z = sigf(iz.y + hz.y);
      float n = tanhf(in_.y + r * hn.y); out.y = (1.f - z) * n + z * old.y; }
    { float r = sigf(ir.z + hr.z), z = sigf(iz.z + hz.z);
      float n = tanhf(in_.z + r * hn.z); out.z = (1.f - z) * n + z * old.z; }
    { float r = sigf(ir.w + hr.w), z = sigf(iz.w + hz.w);
      float n = tanhf(in_.w + r * hn.w); out.w = (1.f - z) * n + z * old.w; }

    *(float4*)(g_state + (size_t)m * HH + c) = out;
    fp16* base = g_state_e + (size_t)m * 2 * HH;
    hilo4(out, base + c, base + HH + c);
}

// head diff -> ext [B, 2H]
__global__ void dd_cvt_k()
{
    int gid = blockIdx.x * blockDim.x + threadIdx.x;     // B * 128
    if (gid >= BB * (HH / 4)) return;
    int row = gid >> 7, c = (gid & 127) * 4;
    float4 a = *(const float4*)(g_state + (size_t)row * HH + c);
    float4 b = *(const float4*)(g_state + (size_t)(row + 2 * BB) * HH + c);
    a.x -= b.x; a.y -= b.y; a.z -= b.z; a.w -= b.w;
    fp16* base = g_ddv_e + (size_t)row * 2 * HH;
    hilo4(a, base + c, base + HH + c);
}

// final head: out[B,32] = hh[B,512] @ W2[512,32] + b2 (fp32, tiny)
__global__ void head2_k(const float* __restrict__ W2, const float* __restrict__ b2,
                        float* __restrict__ out)
{
    int r = threadIdx.x >> 5, col = threadIdx.x & 31;
    int row = blockIdx.x * 8 + r;
    const float* h = g_hh + (size_t)row * HH;
    float acc = b2[col];
#pragma unroll 8
    for (int k = 0; k < HH; k++)
        acc = fmaf(h[k], W2[k * RR + col], acc);
    out[(size_t)row * RR + col] = acc;
}

// ---------------------------------------------------------------------------
// Host launch
// ---------------------------------------------------------------------------
template<int EPI, int OUT, int PASSES>
static void rg(const fp16* A, const fp16* W, float* C, fp16* E,
               const float* bias, const float* aux, int M, int N, int K)
{
    dim3 grid(N / 128, M / 128);
    hgemm_k<EPI, OUT, PASSES><<<grid, 256>>>(A, W, C, E, bias, aux, M, N, K);
}

extern "C" void kernel_launch(void* const* d_in, const int* in_sizes, int n_in,
                              void* d_out, int out_size)
{
    const int*   a_ids   = (const int*)  d_in[0];
    const int*   ev_ids  = (const int*)  d_in[1];
    const int*   b_ids   = (const int*)  d_in[2];
    const int*   c_ids   = (const int*)  d_in[3];
    const float* text_ab = (const float*)d_in[4];
    const float* ent     = (const float*)d_in[5];
    const float* text_W  = (const float*)d_in[6];
    const float* text_b  = (const float*)d_in[7];
    const float* proj_W  = (const float*)d_in[8];
    const float* proj_b  = (const float*)d_in[9];
    const float* msg_W1  = (const float*)d_in[10];
    const float* msg_b1  = (const float*)d_in[11];
    const float* msg_W2  = (const float*)d_in[12];
    const float* msg_b2  = (const float*)d_in[13];
    const float* att_W1  = (const float*)d_in[14];
    const float* att_b1  = (const float*)d_in[15];
    const float* att_W2  = (const float*)d_in[16];
    const float* att_b2  = (const float*)d_in[17];
    const float* gru_Wih = (const float*)d_in[18];
    const float* gru_Whh = (const float*)d_in[19];
    const float* gru_bih = (const float*)d_in[20];
    const float* gru_bhh = (const float*)d_in[21];
    const float* head_W1 = (const float*)d_in[22];
    const float* head_b1 = (const float*)d_in[23];
    const float* head_W2 = (const float*)d_in[24];
    const float* head_b2 = (const float*)d_in[25];
    float* out = (float*)d_out;

    float *tx, *state, *msgp, *gi, *gh, *hh;
    fp16 *text_e, *emb4_e, *state_e, *diff_e, *hidm_e, *hida_e, *msgatt_e, *ddv_e;
    fp16 *textW, *projW, *msgW1h, *msgW2h, *attW1h, *attW2h, *Wihh, *Whhh, *headW1h;
    cudaGetSymbolAddress((void**)&tx,       g_tx);
    cudaGetSymbolAddress((void**)&state,    g_state);
    cudaGetSymbolAddress((void**)&msgp,     g_msg);
    cudaGetSymbolAddress((void**)&gi,       g_gi);
    cudaGetSymbolAddress((void**)&gh,       g_gh);
    cudaGetSymbolAddress((void**)&hh,       g_hh);
    cudaGetSymbolAddress((void**)&text_e,   g_text_e);
    cudaGetSymbolAddress((void**)&emb4_e,   g_emb4_e);
    cudaGetSymbolAddress((void**)&state_e,  g_state_e);
    cudaGetSymbolAddress((void**)&diff_e,   g_diff_e);
    cudaGetSymbolAddress((void**)&hidm_e,   g_hidm_e);
    cudaGetSymbolAddress((void**)&hida_e,   g_hida_e);
    cudaGetSymbolAddress((void**)&msgatt_e, g_msgatt_e);
    cudaGetSymbolAddress((void**)&ddv_e,    g_ddv_e);
    cudaGetSymbolAddress((void**)&textW,    g_textW_h);
    cudaGetSymbolAddress((void**)&projW,    g_projW_h);
    cudaGetSymbolAddress((void**)&msgW1h,   g_msgW1_h);
    cudaGetSymbolAddress((void**)&msgW2h,   g_msgW2_h);
    cudaGetSymbolAddress((void**)&attW1h,   g_attW1_h);
    cudaGetSymbolAddress((void**)&attW2h,   g_attW2_h);
    cudaGetSymbolAddress((void**)&Wihh,     g_Wih_h);
    cudaGetSymbolAddress((void**)&Whhh,     g_Whh_h);
    cudaGetSymbolAddress((void**)&headW1h,  g_headW1_h);

    auto cvw = [](const float* W, fp16* E, int KN) {
        cvt_w_k<<<(KN / 4 + 255) / 256, 256>>>(W, E, KN);
    };

    cvw(text_W, textW, TT * DD);                                          // 0
    cvt_text_k<<<(BB * (TT / 4) + 255) / 256, 256>>>(text_ab);            // 1
    rg<1, 1, 1>(text_e, textW, tx, nullptr, text_b, nullptr, BB, DD, TT); // 2 (1-pass)
    cvw(proj_W, projW, DD * HH);                                          // 3
    gather_emb_k<<<(4 * BB * (DD / 4) + 255) / 256, 256>>>(a_ids, ev_ids, b_ids, c_ids, ent); // 4
    rg<1, 3, 2>(emb4_e, projW, state, state_e, proj_b, nullptr, 4 * BB, HH, DD);              // 5

    // remaining weight conversions
    for (int l = 0; l < 2; l++) {
        cvw(msg_W1 + (size_t)l * 520 * HH,     msgW1h + (size_t)l * HH * HH, HH * HH);
        cvw(msg_W2 + (size_t)l * HH * HH,      msgW2h + (size_t)l * HH * HH, HH * HH);
        cvw(att_W1 + (size_t)l * 520 * (HH/2), attW1h + (size_t)l * HH * (HH/2), HH * (HH/2));
        cvw(att_W2 + (size_t)l * (HH/2) * HH,  attW2h + (size_t)l * (HH/2) * HH, (HH/2) * HH);
        int tot = HH * G3H;
        cvt_w_gru_k<<<(tot + 255) / 256, 256>>>(gru_Wih + (size_t)l * G3H * HH,
                                                Wihh + (size_t)l * HH * G3H);
        cvt_w_gru_k<<<(tot + 255) / 256, 256>>>(gru_Whh + (size_t)l * G3H * HH,
                                                Whhh + (size_t)l * HH * G3H);
    }
    cvw(head_W1, headW1h, HH * HH);

    const int ew = 4 * BB * (HH / 4);
    const int ed = 3 * BB * (HH / 4);

    for (int ii = 0; ii < 2; ii++) {
        if (ii) relu_state_k<<<(ew + 255) / 256, 256>>>();
        const float* mW1 = msg_W1 + (size_t)ii * 520 * HH;
        const float* aW1 = att_W1 + (size_t)ii * 520 * (HH / 2);
        for (int p = 0; p < 2; p++) {
            diff_cvt_k<<<(ed + 255) / 256, 256>>>();
            // hidm_e = relu(diff @ W1 + b1 + edgebias)          [2-pass]
            rg<2, 2, 2>(diff_e, msgW1h + (size_t)ii * HH * HH,
                        nullptr, hidm_e, msg_b1 + ii * HH, mW1 + 512 * HH,
                        3 * BB, HH, HH);
            // msg = hidm @ W2 + b2 (fp32)                        [2-pass]
            rg<0, 1, 2>(hidm_e, msgW2h + (size_t)ii * HH * HH,
                        msgp, nullptr, msg_b2 + ii * HH, nullptr, 3 * BB, HH, HH);
            // hida_e = relu(diff @ attW1 + b + edgebias)         [1-pass]
            rg<2, 2, 1>(diff_e, attW1h + (size_t)ii * HH * (HH/2),
                        nullptr, hida_e, att_b1 + ii * (HH / 2), aW1 + 512 * (HH / 2),
                        3 * BB, HH / 2, HH);
            // msgatt_e = msg * sigmoid(hida @ attW2 + b)         [1-pass]
            rg<3, 2, 1>(hida_e, attW2h + (size_t)ii * (HH/2) * HH,
                        nullptr, msgatt_e, att_b2 + ii * HH, msgp, 3 * BB, HH, HH / 2);
            // gi = msgatt @ Wih^T + bih                          [1-pass]
            rg<0, 1, 1>(msgatt_e, Wihh + (size_t)ii * HH * G3H,
                        gi, nullptr, gru_bih + ii * G3H, nullptr, 3 * BB, G3H, HH);
            // gh = state @ Whh^T + bhh                           [1-pass]
            rg<0, 1, 1>(state_e, Whhh + (size_t)ii * HH * G3H,
                        gh, nullptr, gru_bhh + ii * G3H, nullptr, 4 * BB, G3H, HH);
            // GRU update
            gru_k<<<(ew + 255) / 256, 256>>>(gru_bih + ii * G3H);
        }
    }

    // ---- head ----
    dd_cvt_k<<<(BB * (HH / 4) + 255) / 256, 256>>>();
    rg<1, 1, 2>(ddv_e, headW1h, hh, nullptr, head_b1, nullptr, BB, HH, HH);
    head2_k<<<BB / 8, 256>>>(head_W2, head_b2, out);
}

// round 12
// speedup vs baseline: 1.8263x; 1.1949x over previous
#include <cuda_runtime.h>
#include <cuda_fp16.h>
#include <math.h>
#include <stdint.h>
#include <stddef.h>

// Problem constants
#define BB   16384            // batch / paths
#define DD   256              // embedding dim
#define HH   512              // hidden dim
#define TT   768              // text dim
#define RR   32               // relation classes
#define G3H  1536             // 3*H

typedef __half  fp16;
typedef __half2 fp162;

// ---------------------------------------------------------------------------
// Scratch. "_e" buffers keep the [M,2K] ext layout (cols [0,K)=hi, [K,2K)=lo)
// but ALL GEMMs are now 1-pass: only the hi halves are written/read.
// Weights: PLAIN fp16 [K,N].
// ---------------------------------------------------------------------------
__device__ __align__(128) float g_tx   [(size_t)BB * DD];
__device__ __align__(128) float g_state[(size_t)4 * BB * HH];
__device__ __align__(128) float g_msg  [(size_t)3 * BB * HH];
__device__ __align__(128) float g_gi   [(size_t)3 * BB * G3H];
__device__ __align__(128) float g_gh   [(size_t)4 * BB * G3H];
__device__ __align__(128) float g_hh   [(size_t)BB * HH];

__device__ __align__(128) fp16 g_text_e  [(size_t)BB * 2 * TT];
__device__ __align__(128) fp16 g_emb4_e  [(size_t)4 * BB * 2 * DD];
__device__ __align__(128) fp16 g_state_e [(size_t)4 * BB * 2 * HH];
__device__ __align__(128) fp16 g_diff_e  [(size_t)3 * BB * 2 * HH];
__device__ __align__(128) fp16 g_hidm_e  [(size_t)3 * BB * 2 * HH];
__device__ __align__(128) fp16 g_hida_e  [(size_t)3 * BB * HH];        // 2*(H/2)
__device__ __align__(128) fp16 g_msgatt_e[(size_t)3 * BB * 2 * HH];
__device__ __align__(128) fp16 g_ddv_e   [(size_t)BB * 2 * HH];

// plain fp16 weights [K,N]
__device__ __align__(128) fp16 g_textW_h [(size_t)TT * DD];
__device__ __align__(128) fp16 g_projW_h [(size_t)DD * HH];
__device__ __align__(128) fp16 g_msgW1_h [2][(size_t)HH * HH];
__device__ __align__(128) fp16 g_msgW2_h [2][(size_t)HH * HH];
__device__ __align__(128) fp16 g_attW1_h [2][(size_t)HH * (HH/2)];
__device__ __align__(128) fp16 g_attW2_h [2][(size_t)(HH/2) * HH];
__device__ __align__(128) fp16 g_Wih_h   [2][(size_t)HH * G3H];
__device__ __align__(128) fp16 g_Whh_h   [2][(size_t)HH * G3H];
__device__ __align__(128) fp16 g_headW1_h[(size_t)HH * HH];

// ---------------------------------------------------------------------------
// Small helpers
// ---------------------------------------------------------------------------
__device__ __forceinline__ uint32_t smem_u32(const void* p) {
    return (uint32_t)__cvta_generic_to_shared(p);
}
__device__ __forceinline__ void cp16c(void* s, const void* g) {
    asm volatile("cp.async.cg.shared.global [%0], [%1], 16;\n"
                 :: "r"(smem_u32(s)), "l"(g));
}
__device__ __forceinline__ void cp_commit() {
    asm volatile("cp.async.commit_group;\n");
}
__device__ __forceinline__ void cp_wait0() {
    asm volatile("cp.async.wait_group 0;\n");
}
__device__ __forceinline__ void cp_wait1() {
    asm volatile("cp.async.wait_group 1;\n");
}
#define LDSM_X4(r0,r1,r2,r3,addr) \
    asm volatile("ldmatrix.sync.aligned.m8n8.x4.shared.b16 {%0,%1,%2,%3}, [%4];" \
        : "=r"(r0),"=r"(r1),"=r"(r2),"=r"(r3) : "r"(addr))
#define LDSM_X4T(r0,r1,r2,r3,addr) \
    asm volatile("ldmatrix.sync.aligned.m8n8.x4.trans.shared.b16 {%0,%1,%2,%3}, [%4];" \
        : "=r"(r0),"=r"(r1),"=r"(r2),"=r"(r3) : "r"(addr))
__device__ __forceinline__ void mma16816(float* d, const uint32_t* a, const uint32_t* b) {
    asm volatile(
        "mma.sync.aligned.m16n8k16.row.col.f32.f16.f16.f32 "
        "{%0,%1,%2,%3},{%4,%5,%6,%7},{%8,%9},{%0,%1,%2,%3};"
        : "+f"(d[0]), "+f"(d[1]), "+f"(d[2]), "+f"(d[3])
        : "r"(a[0]), "r"(a[1]), "r"(a[2]), "r"(a[3]), "r"(b[0]), "r"(b[1]));
}

__device__ __forceinline__ float sigf(float x) { return 1.f / (1.f + expf(-x)); }

// write 4 fp32 values as fp16 (hi only — lo halves are dead with 1-pass GEMMs)
__device__ __forceinline__ void hi4(float4 v, fp16* hp) {
    ((fp162*)hp)[0] = __halves2half2(__float2half_rn(v.x), __float2half_rn(v.y));
    ((fp162*)hp)[1] = __halves2half2(__float2half_rn(v.z), __float2half_rn(v.w));
}

// ---------------------------------------------------------------------------
// fp16 tensor-core GEMM, hi/lo compensation on A (PASSES = 2) or plain (1).
// A: [M, 2K] ext fp16 (hi in cols [0,K)), W: [K, N] plain fp16.
// EPI: 0 = +bias, 1 = relu(+bias), 2 = relu(+bias + aux[m>>14][n]),
//      3 = aux[m,n] * sigmoid(+bias)
// OUT bit0: fp32 C[m*N+n]; bit1: ext fp16 E (hi half only)
// Tile 128x128x32, 256 threads (8 warps: 4 along M x 2 along N).
// ---------------------------------------------------------------------------
template<int EPI, int OUT, int PASSES>
__global__ __launch_bounds__(256)
void hgemm_k(const fp16* __restrict__ A, const fp16* __restrict__ W,
             float* __restrict__ C, fp16* __restrict__ E,
             const float* __restrict__ bias, const float* __restrict__ aux,
             int M, int N, int K)
{
    __shared__ __align__(16) fp16 sA[2][128][40];   // 32 + 8 pad
    __shared__ __align__(16) fp16 sB[2][32][136];   // 128 + 8 pad

    const int tid = threadIdx.x;
    const int m0 = blockIdx.y * 128, n0 = blockIdx.x * 128;
    const int warp = tid >> 5, lane = tid & 31;
    const int wm = warp & 3, wn = warp >> 2;

    const int kIters = K >> 5;
    const int T = PASSES * kIters;
    const size_t lda = 2 * (size_t)K;

    float acc[2][8][4];
#pragma unroll
    for (int i = 0; i < 2; i++)
#pragma unroll
        for (int j = 0; j < 8; j++)
#pragma unroll
            for (int q = 0; q < 4; q++) acc[i][j][q] = 0.f;

    const int arow = tid >> 1, acc0 = (tid & 1) * 16;
    const int brow = tid >> 3, bcc0 = (tid & 7) * 16;

    auto load_tile = [&](int it, int buf) {
        int p  = it / kIters;                 // 0: hi, 1: lo
        int kb = it - p * kIters;
        int k0 = kb << 5;
        int aoff = (p == 1) ? K : 0;
        const fp16* ga = A + (size_t)(m0 + arow) * lda + aoff + k0 + acc0;
        cp16c(&sA[buf][arow][acc0],     ga);
        cp16c(&sA[buf][arow][acc0 + 8], ga + 8);
        const fp16* gb = W + (size_t)(k0 + brow) * N + n0 + bcc0;
        cp16c(&sB[buf][brow][bcc0],     gb);
        cp16c(&sB[buf][brow][bcc0 + 8], gb + 8);
        cp_commit();
    };

    load_tile(0, 0);

    for (int it = 0; it < T; ++it) {
        const int buf = it & 1;
        if (it + 1 < T) { load_tile(it + 1, buf ^ 1); cp_wait1(); }
        else            { cp_wait0(); }
        __syncthreads();

#pragma unroll
        for (int kk = 0; kk < 2; ++kk) {
            uint32_t afrag[2][4];
#pragma unroll
            for (int mt = 0; mt < 2; ++mt) {
                int r = wm * 32 + mt * 16 + (lane & 15);
                int c = kk * 16 + ((lane >> 4) << 3);
                LDSM_X4(afrag[mt][0], afrag[mt][1], afrag[mt][2], afrag[mt][3],
                        smem_u32(&sA[buf][r][c]));
            }
            uint32_t bfrag[8][2];
#pragma unroll
            for (int tp = 0; tp < 4; ++tp) {
                int g = lane >> 3, lr = lane & 7;
                int row = kk * 16 + ((g & 1) << 3) + lr;
                int col = wn * 64 + tp * 16 + ((g >> 1) << 3);
                uint32_t r0, r1, r2, r3;
                LDSM_X4T(r0, r1, r2, r3, smem_u32(&sB[buf][row][col]));
                bfrag[tp * 2][0] = r0;     bfrag[tp * 2][1] = r1;
                bfrag[tp * 2 + 1][0] = r2; bfrag[tp * 2 + 1][1] = r3;
            }
#pragma unroll
            for (int mt = 0; mt < 2; ++mt)
#pragma unroll
                for (int nt = 0; nt < 8; ++nt)
                    mma16816(acc[mt][nt], afrag[mt], bfrag[nt]);
        }
        __syncthreads();
    }

    // epilogue
    const int r0 = lane >> 2, c0 = (lane & 3) * 2;
#pragma unroll
    for (int mt = 0; mt < 2; ++mt) {
#pragma unroll
        for (int half = 0; half < 2; ++half) {
            const int m = m0 + wm * 32 + mt * 16 + r0 + half * 8;
            const int et = m >> 14;
#pragma unroll
            for (int nt = 0; nt < 8; ++nt) {
                const int n = n0 + wn * 64 + nt * 8 + c0;
                float v0 = acc[mt][nt][half * 2 + 0] + bias[n];
                float v1 = acc[mt][nt][half * 2 + 1] + bias[n + 1];
                if (EPI == 2) {
                    v0 += aux[(size_t)et * N + n];
                    v1 += aux[(size_t)et * N + n + 1];
                }
                if (EPI == 1 || EPI == 2) { v0 = fmaxf(v0, 0.f); v1 = fmaxf(v1, 0.f); }
                if (EPI == 3) {
                    v0 = aux[(size_t)m * N + n]     * sigf(v0);
                    v1 = aux[(size_t)m * N + n + 1] * sigf(v1);
                }
                if (OUT & 1) {
                    float2 fv = {v0, v1};
                    *(float2*)&C[(size_t)m * N + n] = fv;
                }
                if (OUT & 2) {
                    fp16* base = E + (size_t)m * 2 * N;
                    *(fp162*)(base + n) = __halves2half2(
                        __float2half_rn(v0), __float2half_rn(v1));
                }
            }
        }
    }
}

// ---------------------------------------------------------------------------
// Conversion / elementwise kernels
// ---------------------------------------------------------------------------

// fp32 W[K,N] -> plain fp16 [K,N]
__global__ void cvt_w_k(const float* __restrict__ W, fp16* __restrict__ E, int KN)
{
    int gid = blockIdx.x * blockDim.x + threadIdx.x;
    if (gid * 4 >= KN) return;
    float4 v = *(const float4*)(W + (size_t)gid * 4);
    fp16* p = E + (size_t)gid * 4;
    ((fp162*)p)[0] = __halves2half2(__float2half_rn(v.x), __float2half_rn(v.y));
    ((fp162*)p)[1] = __halves2half2(__float2half_rn(v.z), __float2half_rn(v.w));
}

// GRU weight (3H,H) row-major -> transposed plain fp16 [H, 3H]
__global__ void cvt_w_gru_k(const float* __restrict__ Wg, fp16* __restrict__ E)
{
    int gid = blockIdx.x * blockDim.x + threadIdx.x;     // over H*3H
    if (gid >= HH * G3H) return;
    int k = gid / G3H, j = gid - k * G3H;
    E[gid] = __float2half_rn(Wg[(size_t)j * HH + k]);
}

// text_ab fp32 [B,T] -> ext [B,2T] (hi only)
__global__ void cvt_text_k(const float* __restrict__ X)
{
    int gid = blockIdx.x * blockDim.x + threadIdx.x;     // B * T/4
    if (gid >= BB * (TT / 4)) return;
    int m = gid / (TT / 4), q = gid - m * (TT / 4);
    float4 v = *(const float4*)(X + (size_t)m * TT + q * 4);
    hi4(v, g_text_e + (size_t)m * 2 * TT + q * 4);
}

// gather node embeddings (event gets +tx) -> ext [4B, 2D] (hi only)
__global__ void gather_emb_k(const int* __restrict__ a, const int* __restrict__ ev,
                             const int* __restrict__ b, const int* __restrict__ c,
                             const float* __restrict__ ent)
{
    int gid = blockIdx.x * blockDim.x + threadIdx.x;     // 4B * 64
    if (gid >= 4 * BB * (DD / 4)) return;
    int row = gid >> 6, c4 = (gid & 63) * 4;
    int sel = row >> 14, r = row & (BB - 1);
    int id = (sel == 0) ? a[r] : (sel == 1) ? ev[r] : (sel == 2) ? b[r] : c[r];
    float4 v = *(const float4*)(ent + (size_t)id * DD + c4);
    if (sel == 1) {
        float4 tv = *(const float4*)(g_tx + (size_t)r * DD + c4);
        v.x += tv.x; v.y += tv.y; v.z += tv.z; v.w += tv.w;
    }
    hi4(v, g_emb4_e + (size_t)row * 2 * DD + c4);
}

// diff = state[src] - state[dst] -> ext [3B, 2H] (hi only)
__global__ void diff_cvt_k()
{
    int gid = blockIdx.x * blockDim.x + threadIdx.x;     // 3B * 128
    if (gid >= 3 * BB * (HH / 4)) return;
    int row = gid >> 7, c = (gid & 127) * 4;
    int src = (row < 2 * BB) ? row : row - BB;
    float4 s = *(const float4*)(g_state + (size_t)src * HH + c);
    float4 d = *(const float4*)(g_state + (size_t)(row + BB) * HH + c);
    s.x -= d.x; s.y -= d.y; s.z -= d.z; s.w -= d.w;
    hi4(s, g_diff_e + (size_t)row * 2 * HH + c);
}

// state = relu(state), refresh ext (hi only)
__global__ void relu_state_k()
{
    int gid = blockIdx.x * blockDim.x + threadIdx.x;     // 4B * 128
    if (gid >= 4 * BB * (HH / 4)) return;
    int row = gid >> 7, c = (gid & 127) * 4;
    float4 v = *(float4*)(g_state + (size_t)row * HH + c);
    v.x = fmaxf(v.x, 0.f); v.y = fmaxf(v.y, 0.f);
    v.z = fmaxf(v.z, 0.f); v.w = fmaxf(v.w, 0.f);
    *(float4*)(g_state + (size_t)row * HH + c) = v;
    hi4(v, g_state_e + (size_t)row * 2 * HH + c);
}

// GRU elementwise update; writes state fp32 + ext (hi only)
__global__ void gru_k(const float* __restrict__ bih)
{
    int gid = blockIdx.x * blockDim.x + threadIdx.x;     // 4B * 128
    if (gid >= 4 * BB * (HH / 4)) return;
    int m = gid >> 7, c = (gid & 127) * 4;

    const float* ghr = g_gh + (size_t)m * G3H;
    float4 hr = *(const float4*)(ghr + c);
    float4 hz = *(const float4*)(ghr + HH + c);
    float4 hn = *(const float4*)(ghr + 2 * HH + c);

    float4 ir, iz, in_;
    if (m < BB) {
        ir  = *(const float4*)(bih + c);
        iz  = *(const float4*)(bih + HH + c);
        in_ = *(const float4*)(bih + 2 * HH + c);
    } else {
        const float* gir = g_gi + (size_t)(m - BB) * G3H;
        ir  = *(const float4*)(gir + c);
        iz  = *(const float4*)(gir + HH + c);
        in_ = *(const float4*)(gir + 2 * HH + c);
    }
    float4 old = *(const float4*)(g_state + (size_t)m * HH + c);

    float4 out;
    { float r = sigf(ir.x + hr.x), z = sigf(iz.x + hz.x);
      float n = tanhf(in_.x + r * hn.x); out.x = (1.f - z) * n + z * old.x; }
    { float r = sigf(ir.y + hr.y), z = sigf(iz.y + hz.y);
      float n = tanhf(in_.y + r * hn.y); out.y = (1.f - z) * n + z * old.y; }
    { float r = sigf(ir.z + hr.z), z = sigf(iz.z + hz.z);
      float n = tanhf(in_.z + r * hn.z); out.z = (1.f - z) * n + z * old.z; }
    { float r = sigf(ir.w + hr.w), z = sigf(iz.w + hz.w);
      float n = tanhf(in_.w + r * hn.w); out.w = (1.f - z) * n + z * old.w; }

    *(float4*)(g_state + (size_t)m * HH + c) = out;
    hi4(out, g_state_e + (size_t)m * 2 * HH + c);
}

// head diff -> ext [B, 2H] (hi only)
__global__ void dd_cvt_k()
{
    int gid = blockIdx.x * blockDim.x + threadIdx.x;     // B * 128
    if (gid >= BB * (HH / 4)) return;
    int row = gid >> 7, c = (gid & 127) * 4;
    float4 a = *(const float4*)(g_state + (size_t)row * HH + c);
    float4 b = *(const float4*)(g_state + (size_t)(row + 2 * BB) * HH + c);
    a.x -= b.x; a.y -= b.y; a.z -= b.z; a.w -= b.w;
    hi4(a, g_ddv_e + (size_t)row * 2 * HH + c);
}

// final head: out[B,32] = hh[B,512] @ W2[512,32] + b2 (fp32, tiny)
__global__ void head2_k(const float* __restrict__ W2, const float* __restrict__ b2,
                        float* __restrict__ out)
{
    int r = threadIdx.x >> 5, col = threadIdx.x & 31;
    int row = blockIdx.x * 8 + r;
    const float* h = g_hh + (size_t)row * HH;
    float acc = b2[col];
#pragma unroll 8
    for (int k = 0; k < HH; k++)
        acc = fmaf(h[k], W2[k * RR + col], acc);
    out[(size_t)row * RR + col] = acc;
}

// ---------------------------------------------------------------------------
// Host launch
// ---------------------------------------------------------------------------
template<int EPI, int OUT, int PASSES>
static void rg(const fp16* A, const fp16* W, float* C, fp16* E,
               const float* bias, const float* aux, int M, int N, int K)
{
    dim3 grid(N / 128, M / 128);
    hgemm_k<EPI, OUT, PASSES><<<grid, 256>>>(A, W, C, E, bias, aux, M, N, K);
}

extern "C" void kernel_launch(void* const* d_in, const int* in_sizes, int n_in,
                              void* d_out, int out_size)
{
    const int*   a_ids   = (const int*)  d_in[0];
    const int*   ev_ids  = (const int*)  d_in[1];
    const int*   b_ids   = (const int*)  d_in[2];
    const int*   c_ids   = (const int*)  d_in[3];
    const float* text_ab = (const float*)d_in[4];
    const float* ent     = (const float*)d_in[5];
    const float* text_W  = (const float*)d_in[6];
    const float* text_b  = (const float*)d_in[7];
    const float* proj_W  = (const float*)d_in[8];
    const float* proj_b  = (const float*)d_in[9];
    const float* msg_W1  = (const float*)d_in[10];
    const float* msg_b1  = (const float*)d_in[11];
    const float* msg_W2  = (const float*)d_in[12];
    const float* msg_b2  = (const float*)d_in[13];
    const float* att_W1  = (const float*)d_in[14];
    const float* att_b1  = (const float*)d_in[15];
    const float* att_W2  = (const float*)d_in[16];
    const float* att_b2  = (const float*)d_in[17];
    const float* gru_Wih = (const float*)d_in[18];
    const float* gru_Whh = (const float*)d_in[19];
    const float* gru_bih = (const float*)d_in[20];
    const float* gru_bhh = (const float*)d_in[21];
    const float* head_W1 = (const float*)d_in[22];
    const float* head_b1 = (const float*)d_in[23];
    const float* head_W2 = (const float*)d_in[24];
    const float* head_b2 = (const float*)d_in[25];
    float* out = (float*)d_out;

    float *tx, *state, *msgp, *gi, *gh, *hh;
    fp16 *text_e, *emb4_e, *state_e, *diff_e, *hidm_e, *hida_e, *msgatt_e, *ddv_e;
    fp16 *textW, *projW, *msgW1h, *msgW2h, *attW1h, *attW2h, *Wihh, *Whhh, *headW1h;
    cudaGetSymbolAddress((void**)&tx,       g_tx);
    cudaGetSymbolAddress((void**)&state,    g_state);
    cudaGetSymbolAddress((void**)&msgp,     g_msg);
    cudaGetSymbolAddress((void**)&gi,       g_gi);
    cudaGetSymbolAddress((void**)&gh,       g_gh);
    cudaGetSymbolAddress((void**)&hh,       g_hh);
    cudaGetSymbolAddress((void**)&text_e,   g_text_e);
    cudaGetSymbolAddress((void**)&emb4_e,   g_emb4_e);
    cudaGetSymbolAddress((void**)&state_e,  g_state_e);
    cudaGetSymbolAddress((void**)&diff_e,   g_diff_e);
    cudaGetSymbolAddress((void**)&hidm_e,   g_hidm_e);
    cudaGetSymbolAddress((void**)&hida_e,   g_hida_e);
    cudaGetSymbolAddress((void**)&msgatt_e, g_msgatt_e);
    cudaGetSymbolAddress((void**)&ddv_e,    g_ddv_e);
    cudaGetSymbolAddress((void**)&textW,    g_textW_h);
    cudaGetSymbolAddress((void**)&projW,    g_projW_h);
    cudaGetSymbolAddress((void**)&msgW1h,   g_msgW1_h);
    cudaGetSymbolAddress((void**)&msgW2h,   g_msgW2_h);
    cudaGetSymbolAddress((void**)&attW1h,   g_attW1_h);
    cudaGetSymbolAddress((void**)&attW2h,   g_attW2_h);
    cudaGetSymbolAddress((void**)&Wihh,     g_Wih_h);
    cudaGetSymbolAddress((void**)&Whhh,     g_Whh_h);
    cudaGetSymbolAddress((void**)&headW1h,  g_headW1_h);

    auto cvw = [](const float* W, fp16* E, int KN) {
        cvt_w_k<<<(KN / 4 + 255) / 256, 256>>>(W, E, KN);
    };

    cvw(text_W, textW, TT * DD);                                          // 0
    cvt_text_k<<<(BB * (TT / 4) + 255) / 256, 256>>>(text_ab);            // 1
    rg<1, 1, 1>(text_e, textW, tx, nullptr, text_b, nullptr, BB, DD, TT); // 2
    cvw(proj_W, projW, DD * HH);                                          // 3
    gather_emb_k<<<(4 * BB * (DD / 4) + 255) / 256, 256>>>(a_ids, ev_ids, b_ids, c_ids, ent); // 4
    rg<1, 3, 1>(emb4_e, projW, state, state_e, proj_b, nullptr, 4 * BB, HH, DD);              // 5

    // remaining weight conversions
    for (int l = 0; l < 2; l++) {
        cvw(msg_W1 + (size_t)l * 520 * HH,     msgW1h + (size_t)l * HH * HH, HH * HH);
        cvw(msg_W2 + (size_t)l * HH * HH,      msgW2h + (size_t)l * HH * HH, HH * HH);
        cvw(att_W1 + (size_t)l * 520 * (HH/2), attW1h + (size_t)l * HH * (HH/2), HH * (HH/2));
        cvw(att_W2 + (size_t)l * (HH/2) * HH,  attW2h + (size_t)l * (HH/2) * HH, (HH/2) * HH);
        int tot = HH * G3H;
        cvt_w_gru_k<<<(tot + 255) / 256, 256>>>(gru_Wih + (size_t)l * G3H * HH,
                                                Wihh + (size_t)l * HH * G3H);
        cvt_w_gru_k<<<(tot + 255) / 256, 256>>>(gru_Whh + (size_t)l * G3H * HH,
                                                Whhh + (size_t)l * HH * G3H);
    }
    cvw(head_W1, headW1h, HH * HH);

    const int ew = 4 * BB * (HH / 4);
    const int ed = 3 * BB * (HH / 4);

    for (int ii = 0; ii < 2; ii++) {
        if (ii) relu_state_k<<<(ew + 255) / 256, 256>>>();
        const float* mW1 = msg_W1 + (size_t)ii * 520 * HH;
        const float* aW1 = att_W1 + (size_t)ii * 520 * (HH / 2);
        for (int p = 0; p < 2; p++) {
            diff_cvt_k<<<(ed + 255) / 256, 256>>>();
            // hidm_e = relu(diff @ W1 + b1 + edgebias)          [1-pass]
            rg<2, 2, 1>(diff_e, msgW1h + (size_t)ii * HH * HH,
                        nullptr, hidm_e, msg_b1 + ii * HH, mW1 + 512 * HH,
                        3 * BB, HH, HH);
            // msg = hidm @ W2 + b2 (fp32)                        [1-pass]
            rg<0, 1, 1>(hidm_e, msgW2h + (size_t)ii * HH * HH,
                        msgp, nullptr, msg_b2 + ii * HH, nullptr, 3 * BB, HH, HH);
            // hida_e = relu(diff @ attW1 + b + edgebias)         [1-pass]
            rg<2, 2, 1>(diff_e, attW1h + (size_t)ii * HH * (HH/2),
                        nullptr, hida_e, att_b1 + ii * (HH / 2), aW1 + 512 * (HH / 2),
                        3 * BB, HH / 2, HH);
            // msgatt_e = msg * sigmoid(hida @ attW2 + b)         [1-pass]
            rg<3, 2, 1>(hida_e, attW2h + (size_t)ii * (HH/2) * HH,
                        nullptr, msgatt_e, att_b2 + ii * HH, msgp, 3 * BB, HH, HH / 2);
            // gi = msgatt @ Wih^T + bih                          [1-pass]
            rg<0, 1, 1>(msgatt_e, Wihh + (size_t)ii * HH * G3H,
                        gi, nullptr, gru_bih + ii * G3H, nullptr, 3 * BB, G3H, HH);
            // gh = state @ Whh^T + bhh                           [1-pass]
            rg<0, 1, 1>(state_e, Whhh + (size_t)ii * HH * G3H,
                        gh, nullptr, gru_bhh + ii * G3H, nullptr, 4 * BB, G3H, HH);
            // GRU update
            gru_k<<<(ew + 255) / 256, 256>>>(gru_bih + ii * G3H);
        }
    }

    // ---- head ----
    dd_cvt_k<<<(BB * (HH / 4) + 255) / 256, 256>>>();
    rg<1, 1, 1>(ddv_e, headW1h, hh, nullptr, head_b1, nullptr, BB, HH, HH);
    head2_k<<<BB / 8, 256>>>(head_W2, head_b2, out);
}

// round 15
// speedup vs baseline: 2.5365x; 1.3889x over previous
#include <cuda_runtime.h>
#include <cuda_fp16.h>
#include <math.h>
#include <stdint.h>
#include <stddef.h>

// Problem constants
#define BB   16384            // batch / paths
#define DD   256              // embedding dim
#define HH   512              // hidden dim
#define TT   768              // text dim
#define RR   32               // relation classes
#define G3H  1536             // 3*H

// C nodes (3B:4B) are dead: never a source edge, never read by the head.
// Active nodes: A(0:B), Event(B:2B), B(2B:3B) -> 3B nodes, 2B edges.

typedef __half  fp16;
typedef __half2 fp162;

// ---------------------------------------------------------------------------
// Scratch. "_e" buffers keep the [M,2K] ext layout (hi in cols [0,K)),
// all GEMMs 1-pass (only hi halves live). Weights: PLAIN fp16 [K,N].
// ---------------------------------------------------------------------------
__device__ __align__(128) float g_tx   [(size_t)BB * DD];
__device__ __align__(128) float g_state[(size_t)4 * BB * HH];
__device__ __align__(128) float g_msg  [(size_t)3 * BB * HH];
__device__ __align__(128) float g_gi   [(size_t)3 * BB * G3H];
__device__ __align__(128) float g_gh   [(size_t)4 * BB * G3H];
__device__ __align__(128) float g_hh   [(size_t)BB * HH];

__device__ __align__(128) fp16 g_text_e  [(size_t)BB * 2 * TT];
__device__ __align__(128) fp16 g_emb4_e  [(size_t)4 * BB * 2 * DD];
__device__ __align__(128) fp16 g_state_e [(size_t)4 * BB * 2 * HH];
__device__ __align__(128) fp16 g_diff_e  [(size_t)3 * BB * 2 * HH];
__device__ __align__(128) fp16 g_hidm_e  [(size_t)3 * BB * 2 * HH];
__device__ __align__(128) fp16 g_hida_e  [(size_t)3 * BB * HH];
__device__ __align__(128) fp16 g_msgatt_e[(size_t)3 * BB * 2 * HH];
__device__ __align__(128) fp16 g_ddv_e   [(size_t)BB * 2 * HH];

// plain fp16 weights [K,N]
__device__ __align__(128) fp16 g_textW_h [(size_t)TT * DD];
__device__ __align__(128) fp16 g_projW_h [(size_t)DD * HH];
__device__ __align__(128) fp16 g_msgW1_h [2][(size_t)HH * HH];
__device__ __align__(128) fp16 g_msgW2_h [2][(size_t)HH * HH];
__device__ __align__(128) fp16 g_attW1_h [2][(size_t)HH * (HH/2)];
__device__ __align__(128) fp16 g_attW2_h [2][(size_t)(HH/2) * HH];
__device__ __align__(128) fp16 g_Wih_h   [2][(size_t)HH * G3H];
__device__ __align__(128) fp16 g_Whh_h   [2][(size_t)HH * G3H];
__device__ __align__(128) fp16 g_headW1_h[(size_t)HH * HH];

// ---------------------------------------------------------------------------
// Small helpers
// ---------------------------------------------------------------------------
__device__ __forceinline__ uint32_t smem_u32(const void* p) {
    return (uint32_t)__cvta_generic_to_shared(p);
}
__device__ __forceinline__ void cp16c(void* s, const void* g) {
    asm volatile("cp.async.cg.shared.global [%0], [%1], 16;\n"
                 :: "r"(smem_u32(s)), "l"(g));
}
__device__ __forceinline__ void cp_commit() {
    asm volatile("cp.async.commit_group;\n");
}
__device__ __forceinline__ void cp_wait0() {
    asm volatile("cp.async.wait_group 0;\n");
}
__device__ __forceinline__ void cp_wait1() {
    asm volatile("cp.async.wait_group 1;\n");
}
#define LDSM_X4(r0,r1,r2,r3,addr) \
    asm volatile("ldmatrix.sync.aligned.m8n8.x4.shared.b16 {%0,%1,%2,%3}, [%4];" \
        : "=r"(r0),"=r"(r1),"=r"(r2),"=r"(r3) : "r"(addr))
#define LDSM_X4T(r0,r1,r2,r3,addr) \
    asm volatile("ldmatrix.sync.aligned.m8n8.x4.trans.shared.b16 {%0,%1,%2,%3}, [%4];" \
        : "=r"(r0),"=r"(r1),"=r"(r2),"=r"(r3) : "r"(addr))
__device__ __forceinline__ void mma16816(float* d, const uint32_t* a, const uint32_t* b) {
    asm volatile(
        "mma.sync.aligned.m16n8k16.row.col.f32.f16.f16.f32 "
        "{%0,%1,%2,%3},{%4,%5,%6,%7},{%8,%9},{%0,%1,%2,%3};"
        : "+f"(d[0]), "+f"(d[1]), "+f"(d[2]), "+f"(d[3])
        : "r"(a[0]), "r"(a[1]), "r"(a[2]), "r"(a[3]), "r"(b[0]), "r"(b[1]));
}

__device__ __forceinline__ float sigf(float x) { return 1.f / (1.f + expf(-x)); }

// write 4 fp32 values as fp16 (hi only)
__device__ __forceinline__ void hi4(float4 v, fp16* hp) {
    ((fp162*)hp)[0] = __halves2half2(__float2half_rn(v.x), __float2half_rn(v.y));
    ((fp162*)hp)[1] = __halves2half2(__float2half_rn(v.z), __float2half_rn(v.w));
}

// ---------------------------------------------------------------------------
// fp16 tensor-core GEMM (1-pass; PASSES kept for flexibility).
// A: [M, 2K] ext fp16 (hi in cols [0,K)), W: [K, N] plain fp16.
// EPI: 0 = +bias, 1 = relu(+bias), 2 = relu(+bias + aux[m>>14][n]),
//      3 = aux[m,n] * sigmoid(+bias)
// OUT bit0: fp32 C[m*N+n]; bit1: ext fp16 E (hi half only)
// Tile 128x128x32, 256 threads.
// ---------------------------------------------------------------------------
template<int EPI, int OUT, int PASSES>
__global__ __launch_bounds__(256)
void hgemm_k(const fp16* __restrict__ A, const fp16* __restrict__ W,
             float* __restrict__ C, fp16* __restrict__ E,
             const float* __restrict__ bias, const float* __restrict__ aux,
             int M, int N, int K)
{
    __shared__ __align__(16) fp16 sA[2][128][40];   // 32 + 8 pad
    __shared__ __align__(16) fp16 sB[2][32][136];   // 128 + 8 pad

    const int tid = threadIdx.x;
    const int m0 = blockIdx.y * 128, n0 = blockIdx.x * 128;
    const int warp = tid >> 5, lane = tid & 31;
    const int wm = warp & 3, wn = warp >> 2;

    const int kIters = K >> 5;
    const int T = PASSES * kIters;
    const size_t lda = 2 * (size_t)K;

    float acc[2][8][4];
#pragma unroll
    for (int i = 0; i < 2; i++)
#pragma unroll
        for (int j = 0; j < 8; j++)
#pragma unroll
            for (int q = 0; q < 4; q++) acc[i][j][q] = 0.f;

    const int arow = tid >> 1, acc0 = (tid & 1) * 16;
    const int brow = tid >> 3, bcc0 = (tid & 7) * 16;

    auto load_tile = [&](int it, int buf) {
        int p  = it / kIters;                 // 0: hi, 1: lo
        int kb = it - p * kIters;
        int k0 = kb << 5;
        int aoff = (p == 1) ? K : 0;
        const fp16* ga = A + (size_t)(m0 + arow) * lda + aoff + k0 + acc0;
        cp16c(&sA[buf][arow][acc0],     ga);
        cp16c(&sA[buf][arow][acc0 + 8], ga + 8);
        const fp16* gb = W + (size_t)(k0 + brow) * N + n0 + bcc0;
        cp16c(&sB[buf][brow][bcc0],     gb);
        cp16c(&sB[buf][brow][bcc0 + 8], gb + 8);
        cp_commit();
    };

    load_tile(0, 0);

    for (int it = 0; it < T; ++it) {
        const int buf = it & 1;
        if (it + 1 < T) { load_tile(it + 1, buf ^ 1); cp_wait1(); }
        else            { cp_wait0(); }
        __syncthreads();

#pragma unroll
        for (int kk = 0; kk < 2; ++kk) {
            uint32_t afrag[2][4];
#pragma unroll
            for (int mt = 0; mt < 2; ++mt) {
                int r = wm * 32 + mt * 16 + (lane & 15);
                int c = kk * 16 + ((lane >> 4) << 3);
                LDSM_X4(afrag[mt][0], afrag[mt][1], afrag[mt][2], afrag[mt][3],
                        smem_u32(&sA[buf][r][c]));
            }
            uint32_t bfrag[8][2];
#pragma unroll
            for (int tp = 0; tp < 4; ++tp) {
                int g = lane >> 3, lr = lane & 7;
                int row = kk * 16 + ((g & 1) << 3) + lr;
                int col = wn * 64 + tp * 16 + ((g >> 1) << 3);
                uint32_t r0, r1, r2, r3;
                LDSM_X4T(r0, r1, r2, r3, smem_u32(&sB[buf][row][col]));
                bfrag[tp * 2][0] = r0;     bfrag[tp * 2][1] = r1;
                bfrag[tp * 2 + 1][0] = r2; bfrag[tp * 2 + 1][1] = r3;
            }
#pragma unroll
            for (int mt = 0; mt < 2; ++mt)
#pragma unroll
                for (int nt = 0; nt < 8; ++nt)
                    mma16816(acc[mt][nt], afrag[mt], bfrag[nt]);
        }
        __syncthreads();
    }

    // epilogue
    const int r0 = lane >> 2, c0 = (lane & 3) * 2;
#pragma unroll
    for (int mt = 0; mt < 2; ++mt) {
#pragma unroll
        for (int half = 0; half < 2; ++half) {
            const int m = m0 + wm * 32 + mt * 16 + r0 + half * 8;
            const int et = m >> 14;
#pragma unroll
            for (int nt = 0; nt < 8; ++nt) {
                const int n = n0 + wn * 64 + nt * 8 + c0;
                float v0 = acc[mt][nt][half * 2 + 0] + bias[n];
                float v1 = acc[mt][nt][half * 2 + 1] + bias[n + 1];
                if (EPI == 2) {
                    v0 += aux[(size_t)et * N + n];
                    v1 += aux[(size_t)et * N + n + 1];
                }
                if (EPI == 1 || EPI == 2) { v0 = fmaxf(v0, 0.f); v1 = fmaxf(v1, 0.f); }
                if (EPI == 3) {
                    v0 = aux[(size_t)m * N + n]     * sigf(v0);
                    v1 = aux[(size_t)m * N + n + 1] * sigf(v1);
                }
                if (OUT & 1) {
                    float2 fv = {v0, v1};
                    *(float2*)&C[(size_t)m * N + n] = fv;
                }
                if (OUT & 2) {
                    fp16* base = E + (size_t)m * 2 * N;
                    *(fp162*)(base + n) = __halves2half2(
                        __float2half_rn(v0), __float2half_rn(v1));
                }
            }
        }
    }
}

// ---------------------------------------------------------------------------
// Conversion / elementwise kernels
// ---------------------------------------------------------------------------

// fp32 W[K,N] -> plain fp16 [K,N]
__global__ void cvt_w_k(const float* __restrict__ W, fp16* __restrict__ E, int KN)
{
    int gid = blockIdx.x * blockDim.x + threadIdx.x;
    if (gid * 4 >= KN) return;
    float4 v = *(const float4*)(W + (size_t)gid * 4);
    fp16* p = E + (size_t)gid * 4;
    ((fp162*)p)[0] = __halves2half2(__float2half_rn(v.x), __float2half_rn(v.y));
    ((fp162*)p)[1] = __halves2half2(__float2half_rn(v.z), __float2half_rn(v.w));
}

// GRU weight (3H,H) row-major -> transposed plain fp16 [H, 3H]
__global__ void cvt_w_gru_k(const float* __restrict__ Wg, fp16* __restrict__ E)
{
    int gid = blockIdx.x * blockDim.x + threadIdx.x;     // over H*3H
    if (gid >= HH * G3H) return;
    int k = gid / G3H, j = gid - k * G3H;
    E[gid] = __float2half_rn(Wg[(size_t)j * HH + k]);
}

// text_ab fp32 [B,T] -> ext [B,2T] (hi only)
__global__ void cvt_text_k(const float* __restrict__ X)
{
    int gid = blockIdx.x * blockDim.x + threadIdx.x;     // B * T/4
    if (gid >= BB * (TT / 4)) return;
    int m = gid / (TT / 4), q = gid - m * (TT / 4);
    float4 v = *(const float4*)(X + (size_t)m * TT + q * 4);
    hi4(v, g_text_e + (size_t)m * 2 * TT + q * 4);
}

// gather node embeddings for ACTIVE nodes only: A, Event, B (3B rows)
__global__ void gather_emb_k(const int* __restrict__ a, const int* __restrict__ ev,
                             const int* __restrict__ b,
                             const float* __restrict__ ent)
{
    int gid = blockIdx.x * blockDim.x + threadIdx.x;     // 3B * 64
    if (gid >= 3 * BB * (DD / 4)) return;
    int row = gid >> 6, c4 = (gid & 63) * 4;
    int sel = row >> 14, r = row & (BB - 1);
    int id = (sel == 0) ? a[r] : (sel == 1) ? ev[r] : b[r];
    float4 v = *(const float4*)(ent + (size_t)id * DD + c4);
    if (sel == 1) {
        float4 tv = *(const float4*)(g_tx + (size_t)r * DD + c4);
        v.x += tv.x; v.y += tv.y; v.z += tv.z; v.w += tv.w;
    }
    hi4(v, g_emb4_e + (size_t)row * 2 * DD + c4);
}

// diff = state[src] - state[dst] -> ext [2B, 2H] (hi only)
// Edges: row<B: A->Event; row in [B,2B): Event->B. src = row, dst = row + B.
__global__ void diff_cvt_k()
{
    int gid = blockIdx.x * blockDim.x + threadIdx.x;     // 2B * 128
    if (gid >= 2 * BB * (HH / 4)) return;
    int row = gid >> 7, c = (gid & 127) * 4;
    float4 s = *(const float4*)(g_state + (size_t)row * HH + c);
    float4 d = *(const float4*)(g_state + (size_t)(row + BB) * HH + c);
    s.x -= d.x; s.y -= d.y; s.z -= d.z; s.w -= d.w;
    hi4(s, g_diff_e + (size_t)row * 2 * HH + c);
}

// state = relu(state) over 3B active nodes, refresh ext (hi only)
__global__ void relu_state_k()
{
    int gid = blockIdx.x * blockDim.x + threadIdx.x;     // 3B * 128
    if (gid >= 3 * BB * (HH / 4)) return;
    int row = gid >> 7, c = (gid & 127) * 4;
    float4 v = *(float4*)(g_state + (size_t)row * HH + c);
    v.x = fmaxf(v.x, 0.f); v.y = fmaxf(v.y, 0.f);
    v.z = fmaxf(v.z, 0.f); v.w = fmaxf(v.w, 0.f);
    *(float4*)(g_state + (size_t)row * HH + c) = v;
    hi4(v, g_state_e + (size_t)row * 2 * HH + c);
}

// GRU elementwise update over 3B active nodes; writes state fp32 + ext hi
__global__ void gru_k(const float* __restrict__ bih)
{
    int gid = blockIdx.x * blockDim.x + threadIdx.x;     // 3B * 128
    if (gid >= 3 * BB * (HH / 4)) return;
    int m = gid >> 7, c = (gid & 127) * 4;

    const float* ghr = g_gh + (size_t)m * G3H;
    float4 hr = *(const float4*)(ghr + c);
    float4 hz = *(const float4*)(ghr + HH + c);
    float4 hn = *(const float4*)(ghr + 2 * HH + c);

    float4 ir, iz, in_;
    if (m < BB) {   // A nodes: no incoming edges -> gi = bih
        ir  = *(const float4*)(bih + c);
        iz  = *(const float4*)(bih + HH + c);
        in_ = *(const float4*)(bih + 2 * HH + c);
    } else {        // Event / B nodes: gi row = m - B
        const float* gir = g_gi + (size_t)(m - BB) * G3H;
        ir  = *(const float4*)(gir + c);
        iz  = *(const float4*)(gir + HH + c);
        in_ = *(const float4*)(gir + 2 * HH + c);
    }
    float4 old = *(const float4*)(g_state + (size_t)m * HH + c);

    float4 out;
    { float r = sigf(ir.x + hr.x), z = sigf(iz.x + hz.x);
      float n = tanhf(in_.x + r * hn.x); out.x = (1.f - z) * n + z * old.x; }
    { float r = sigf(ir.y + hr.y), z = sigf(iz.y + hz.y);
      float n = tanhf(in_.y + r * hn.y); out.y = (1.f - z) * n + z * old.y; }
    { float r = sigf(ir.z + hr.z), z = sigf(iz.z + hz.z);
      float n = tanhf(in_.z + r * hn.z); out.z = (1.f - z) * n + z * old.z; }
    { float r = sigf(ir.w + hr.w), z = sigf(iz.w + hz.w);
      float n = tanhf(in_.w + r * hn.w); out.w = (1.f - z) * n + z * old.w; }

    *(float4*)(g_state + (size_t)m * HH + c) = out;
    hi4(out, g_state_e + (size_t)m * 2 * HH + c);
}

// head diff -> ext [B, 2H] (hi only)
__global__ void dd_cvt_k()
{
    int gid = blockIdx.x * blockDim.x + threadIdx.x;     // B * 128
    if (gid >= BB * (HH / 4)) return;
    int row = gid >> 7, c = (gid & 127) * 4;
    float4 a = *(const float4*)(g_state + (size_t)row * HH + c);
    float4 b = *(const float4*)(g_state + (size_t)(row + 2 * BB) * HH + c);
    a.x -= b.x; a.y -= b.y; a.z -= b.z; a.w -= b.w;
    hi4(a, g_ddv_e + (size_t)row * 2 * HH + c);
}

// final head: out[B,32] = hh[B,512] @ W2[512,32] + b2 (fp32, tiny)
__global__ void head2_k(const float* __restrict__ W2, const float* __restrict__ b2,
                        float* __restrict__ out)
{
    int r = threadIdx.x >> 5, col = threadIdx.x & 31;
    int row = blockIdx.x * 8 + r;
    const float* h = g_hh + (size_t)row * HH;
    float acc = b2[col];
#pragma unroll 8
    for (int k = 0; k < HH; k++)
        acc = fmaf(h[k], W2[k * RR + col], acc);
    out[(size_t)row * RR + col] = acc;
}

// ---------------------------------------------------------------------------
// Host launch
// ---------------------------------------------------------------------------
template<int EPI, int OUT, int PASSES>
static void rg(const fp16* A, const fp16* W, float* C, fp16* E,
               const float* bias, const float* aux, int M, int N, int K)
{
    dim3 grid(N / 128, M / 128);
    hgemm_k<EPI, OUT, PASSES><<<grid, 256>>>(A, W, C, E, bias, aux, M, N, K);
}

extern "C" void kernel_launch(void* const* d_in, const int* in_sizes, int n_in,
                              void* d_out, int out_size)
{
    const int*   a_ids   = (const int*)  d_in[0];
    const int*   ev_ids  = (const int*)  d_in[1];
    const int*   b_ids   = (const int*)  d_in[2];
    const float* text_ab = (const float*)d_in[4];
    const float* ent     = (const float*)d_in[5];
    const float* text_W  = (const float*)d_in[6];
    const float* text_b  = (const float*)d_in[7];
    const float* proj_W  = (const float*)d_in[8];
    const float* proj_b  = (const float*)d_in[9];
    const float* msg_W1  = (const float*)d_in[10];
    const float* msg_b1  = (const float*)d_in[11];
    const float* msg_W2  = (const float*)d_in[12];
    const float* msg_b2  = (const float*)d_in[13];
    const float* att_W1  = (const float*)d_in[14];
    const float* att_b1  = (const float*)d_in[15];
    const float* att_W2  = (const float*)d_in[16];
    const float* att_b2  = (const float*)d_in[17];
    const float* gru_Wih = (const float*)d_in[18];
    const float* gru_Whh = (const float*)d_in[19];
    const float* gru_bih = (const float*)d_in[20];
    const float* gru_bhh = (const float*)d_in[21];
    const float* head_W1 = (const float*)d_in[22];
    const float* head_b1 = (const float*)d_in[23];
    const float* head_W2 = (const float*)d_in[24];
    const float* head_b2 = (const float*)d_in[25];
    float* out = (float*)d_out;

    float *tx, *state, *msgp, *gi, *gh, *hh;
    fp16 *text_e, *emb4_e, *state_e, *diff_e, *hidm_e, *hida_e, *msgatt_e, *ddv_e;
    fp16 *textW, *projW, *msgW1h, *msgW2h, *attW1h, *attW2h, *Wihh, *Whhh, *headW1h;
    cudaGetSymbolAddress((void**)&tx,       g_tx);
    cudaGetSymbolAddress((void**)&state,    g_state);
    cudaGetSymbolAddress((void**)&msgp,     g_msg);
    cudaGetSymbolAddress((void**)&gi,       g_gi);
    cudaGetSymbolAddress((void**)&gh,       g_gh);
    cudaGetSymbolAddress((void**)&hh,       g_hh);
    cudaGetSymbolAddress((void**)&text_e,   g_text_e);
    cudaGetSymbolAddress((void**)&emb4_e,   g_emb4_e);
    cudaGetSymbolAddress((void**)&state_e,  g_state_e);
    cudaGetSymbolAddress((void**)&diff_e,   g_diff_e);
    cudaGetSymbolAddress((void**)&hidm_e,   g_hidm_e);
    cudaGetSymbolAddress((void**)&hida_e,   g_hida_e);
    cudaGetSymbolAddress((void**)&msgatt_e, g_msgatt_e);
    cudaGetSymbolAddress((void**)&ddv_e,    g_ddv_e);
    cudaGetSymbolAddress((void**)&textW,    g_textW_h);
    cudaGetSymbolAddress((void**)&projW,    g_projW_h);
    cudaGetSymbolAddress((void**)&msgW1h,   g_msgW1_h);
    cudaGetSymbolAddress((void**)&msgW2h,   g_msgW2_h);
    cudaGetSymbolAddress((void**)&attW1h,   g_attW1_h);
    cudaGetSymbolAddress((void**)&attW2h,   g_attW2_h);
    cudaGetSymbolAddress((void**)&Wihh,     g_Wih_h);
    cudaGetSymbolAddress((void**)&Whhh,     g_Whh_h);
    cudaGetSymbolAddress((void**)&headW1h,  g_headW1_h);

    auto cvw = [](const float* W, fp16* E, int KN) {
        cvt_w_k<<<(KN / 4 + 255) / 256, 256>>>(W, E, KN);
    };

    cvw(text_W, textW, TT * DD);
    cvt_text_k<<<(BB * (TT / 4) + 255) / 256, 256>>>(text_ab);
    rg<1, 1, 1>(text_e, textW, tx, nullptr, text_b, nullptr, BB, DD, TT);
    cvw(proj_W, projW, DD * HH);
    gather_emb_k<<<(3 * BB * (DD / 4) + 255) / 256, 256>>>(a_ids, ev_ids, b_ids, ent);
    // proj over ACTIVE 3B nodes
    rg<1, 3, 1>(emb4_e, projW, state, state_e, proj_b, nullptr, 3 * BB, HH, DD);

    // remaining weight conversions
    for (int l = 0; l < 2; l++) {
        cvw(msg_W1 + (size_t)l * 520 * HH,     msgW1h + (size_t)l * HH * HH, HH * HH);
        cvw(msg_W2 + (size_t)l * HH * HH,      msgW2h + (size_t)l * HH * HH, HH * HH);
        cvw(att_W1 + (size_t)l * 520 * (HH/2), attW1h + (size_t)l * HH * (HH/2), HH * (HH/2));
        cvw(att_W2 + (size_t)l * (HH/2) * HH,  attW2h + (size_t)l * (HH/2) * HH, (HH/2) * HH);
        int tot = HH * G3H;
        cvt_w_gru_k<<<(tot + 255) / 256, 256>>>(gru_Wih + (size_t)l * G3H * HH,
                                                Wihh + (size_t)l * HH * G3H);
        cvt_w_gru_k<<<(tot + 255) / 256, 256>>>(gru_Whh + (size_t)l * G3H * HH,
                                                Whhh + (size_t)l * HH * G3H);
    }
    cvw(head_W1, headW1h, HH * HH);

    const int ew = 3 * BB * (HH / 4);   // 3B active nodes
    const int ed = 2 * BB * (HH / 4);   // 2B live edges

    for (int ii = 0; ii < 2; ii++) {
        if (ii) relu_state_k<<<(ew + 255) / 256, 256>>>();
        const float* mW1 = msg_W1 + (size_t)ii * 520 * HH;
        const float* aW1 = att_W1 + (size_t)ii * 520 * (HH / 2);
        for (int p = 0; p < 2; p++) {
            diff_cvt_k<<<(ed + 255) / 256, 256>>>();
            // hidm_e = relu(diff @ W1 + b1 + edgebias)            [2B edges]
            rg<2, 2, 1>(diff_e, msgW1h + (size_t)ii * HH * HH,
                        nullptr, hidm_e, msg_b1 + ii * HH, mW1 + 512 * HH,
                        2 * BB, HH, HH);
            // msg = hidm @ W2 + b2 (fp32)
            rg<0, 1, 1>(hidm_e, msgW2h + (size_t)ii * HH * HH,
                        msgp, nullptr, msg_b2 + ii * HH, nullptr, 2 * BB, HH, HH);
            // hida_e = relu(diff @ attW1 + b + edgebias)
            rg<2, 2, 1>(diff_e, attW1h + (size_t)ii * HH * (HH/2),
                        nullptr, hida_e, att_b1 + ii * (HH / 2), aW1 + 512 * (HH / 2),
                        2 * BB, HH / 2, HH);
            // msgatt_e = msg * sigmoid(hida @ attW2 + b)
            rg<3, 2, 1>(hida_e, attW2h + (size_t)ii * (HH/2) * HH,
                        nullptr, msgatt_e, att_b2 + ii * HH, msgp, 2 * BB, HH, HH / 2);
            // gi = msgatt @ Wih^T + bih  (rows -> nodes B..3B)
            rg<0, 1, 1>(msgatt_e, Wihh + (size_t)ii * HH * G3H,
                        gi, nullptr, gru_bih + ii * G3H, nullptr, 2 * BB, G3H, HH);
            // gh = state @ Whh^T + bhh   (3B active nodes)
            rg<0, 1, 1>(state_e, Whhh + (size_t)ii * HH * G3H,
                        gh, nullptr, gru_bhh + ii * G3H, nullptr, 3 * BB, G3H, HH);
            // GRU update over 3B nodes
            gru_k<<<(ew + 255) / 256, 256>>>(gru_bih + ii * G3H);
        }
    }

    // ---- head ----
    dd_cvt_k<<<(BB * (HH / 4) + 255) / 256, 256>>>();
    rg<1, 1, 1>(ddv_e, headW1h, hh, nullptr, head_b1, nullptr, BB, HH, HH);
    head2_k<<<BB / 8, 256>>>(head_W2, head_b2, out);
}

// round 16
// speedup vs baseline: 2.6540x; 1.0463x over previous
#include <cuda_runtime.h>
#include <cuda_fp16.h>
#include <math.h>
#include <stdint.h>
#include <stddef.h>

// Problem constants
#define BB   16384            // batch / paths
#define DD   256              // embedding dim
#define HH   512              // hidden dim
#define TT   768              // text dim
#define RR   32               // relation classes
#define G3H  1536             // 3*H

// C nodes (3B:4B) are dead. Active nodes: A(0:B), Event(B:2B), B(2B:3B).
// 3B nodes, 2B edges (A->Event, Event->B); src=row, dst=row+B.

typedef __half  fp16;
typedef __half2 fp162;

// ---------------------------------------------------------------------------
// Scratch. "_e": ext fp16 [M,2K] layout (hi half live). gi/gh/msg now fp16.
// ---------------------------------------------------------------------------
__device__ __align__(128) float g_tx   [(size_t)BB * DD];
__device__ __align__(128) float g_state[(size_t)4 * BB * HH];
__device__ __align__(128) float g_hh   [(size_t)BB * HH];

__device__ __align__(128) fp16 g_msg_h [(size_t)3 * BB * HH];
__device__ __align__(128) fp16 g_gi_h  [(size_t)3 * BB * G3H];
__device__ __align__(128) fp16 g_gh_h  [(size_t)4 * BB * G3H];

__device__ __align__(128) fp16 g_text_e  [(size_t)BB * 2 * TT];
__device__ __align__(128) fp16 g_emb4_e  [(size_t)4 * BB * 2 * DD];
__device__ __align__(128) fp16 g_state_e [(size_t)4 * BB * 2 * HH];
__device__ __align__(128) fp16 g_diff_e  [(size_t)3 * BB * 2 * HH];
__device__ __align__(128) fp16 g_hidm_e  [(size_t)3 * BB * 2 * HH];
__device__ __align__(128) fp16 g_hida_e  [(size_t)3 * BB * HH];
__device__ __align__(128) fp16 g_msgatt_e[(size_t)3 * BB * 2 * HH];
__device__ __align__(128) fp16 g_ddv_e   [(size_t)BB * 2 * HH];

// plain fp16 weights [K,N]
__device__ __align__(128) fp16 g_textW_h [(size_t)TT * DD];
__device__ __align__(128) fp16 g_projW_h [(size_t)DD * HH];
__device__ __align__(128) fp16 g_msgW1_h [2][(size_t)HH * HH];
__device__ __align__(128) fp16 g_msgW2_h [2][(size_t)HH * HH];
__device__ __align__(128) fp16 g_attW1_h [2][(size_t)HH * (HH/2)];
__device__ __align__(128) fp16 g_attW2_h [2][(size_t)(HH/2) * HH];
__device__ __align__(128) fp16 g_Wih_h   [2][(size_t)HH * G3H];
__device__ __align__(128) fp16 g_Whh_h   [2][(size_t)HH * G3H];
__device__ __align__(128) fp16 g_headW1_h[(size_t)HH * HH];

// ---------------------------------------------------------------------------
// Small helpers
// ---------------------------------------------------------------------------
__device__ __forceinline__ uint32_t smem_u32(const void* p) {
    return (uint32_t)__cvta_generic_to_shared(p);
}
__device__ __forceinline__ void cp16c(void* s, const void* g) {
    asm volatile("cp.async.cg.shared.global [%0], [%1], 16;\n"
                 :: "r"(smem_u32(s)), "l"(g));
}
__device__ __forceinline__ void cp_commit() {
    asm volatile("cp.async.commit_group;\n");
}
__device__ __forceinline__ void cp_wait0() {
    asm volatile("cp.async.wait_group 0;\n");
}
__device__ __forceinline__ void cp_wait1() {
    asm volatile("cp.async.wait_group 1;\n");
}
#define LDSM_X4(r0,r1,r2,r3,addr) \
    asm volatile("ldmatrix.sync.aligned.m8n8.x4.shared.b16 {%0,%1,%2,%3}, [%4];" \
        : "=r"(r0),"=r"(r1),"=r"(r2),"=r"(r3) : "r"(addr))
#define LDSM_X4T(r0,r1,r2,r3,addr) \
    asm volatile("ldmatrix.sync.aligned.m8n8.x4.trans.shared.b16 {%0,%1,%2,%3}, [%4];" \
        : "=r"(r0),"=r"(r1),"=r"(r2),"=r"(r3) : "r"(addr))
__device__ __forceinline__ void mma16816(float* d, const uint32_t* a, const uint32_t* b) {
    asm volatile(
        "mma.sync.aligned.m16n8k16.row.col.f32.f16.f16.f32 "
        "{%0,%1,%2,%3},{%4,%5,%6,%7},{%8,%9},{%0,%1,%2,%3};"
        : "+f"(d[0]), "+f"(d[1]), "+f"(d[2]), "+f"(d[3])
        : "r"(a[0]), "r"(a[1]), "r"(a[2]), "r"(a[3]), "r"(b[0]), "r"(b[1]));
}

__device__ __forceinline__ float sigf(float x) { return 1.f / (1.f + expf(-x)); }

// write 4 fp32 values as fp16
__device__ __forceinline__ void hi4(float4 v, fp16* hp) {
    ((fp162*)hp)[0] = __halves2half2(__float2half_rn(v.x), __float2half_rn(v.y));
    ((fp162*)hp)[1] = __halves2half2(__float2half_rn(v.z), __float2half_rn(v.w));
}
// read 4 fp16 -> float4
__device__ __forceinline__ float4 ld4h(const fp16* p) {
    fp162 a = ((const fp162*)p)[0], b = ((const fp162*)p)[1];
    float2 fa = __half22float2(a), fb = __half22float2(b);
    return make_float4(fa.x, fa.y, fb.x, fb.y);
}

// ---------------------------------------------------------------------------
// fp16 tensor-core GEMM (1-pass).
// A: [M, 2K] ext fp16 (hi in cols [0,K)), W: [K, N] plain fp16.
// EPI: 0 = +bias, 1 = relu(+bias), 2 = relu(+bias + aux[m>>14][n]),
//      3 = auxh[m,n] * sigmoid(+bias)   (auxh = fp16 multiplier)
// OUT: 1 = fp32 C row-major; 2 = ext fp16 E (hi half); 4 = plain fp16 E
// Tile 128x128x32, 256 threads.
// ---------------------------------------------------------------------------
template<int EPI, int OUT, int PASSES>
__global__ __launch_bounds__(256)
void hgemm_k(const fp16* __restrict__ A, const fp16* __restrict__ W,
             float* __restrict__ C, fp16* __restrict__ E,
             const float* __restrict__ bias, const float* __restrict__ aux,
             const fp16* __restrict__ auxh,
             int M, int N, int K)
{
    __shared__ __align__(16) fp16 sA[2][128][40];   // 32 + 8 pad
    __shared__ __align__(16) fp16 sB[2][32][136];   // 128 + 8 pad

    const int tid = threadIdx.x;
    const int m0 = blockIdx.y * 128, n0 = blockIdx.x * 128;
    const int warp = tid >> 5, lane = tid & 31;
    const int wm = warp & 3, wn = warp >> 2;

    const int kIters = K >> 5;
    const int T = PASSES * kIters;
    const size_t lda = 2 * (size_t)K;

    float acc[2][8][4];
#pragma unroll
    for (int i = 0; i < 2; i++)
#pragma unroll
        for (int j = 0; j < 8; j++)
#pragma unroll
            for (int q = 0; q < 4; q++) acc[i][j][q] = 0.f;

    const int arow = tid >> 1, acc0 = (tid & 1) * 16;
    const int brow = tid >> 3, bcc0 = (tid & 7) * 16;

    auto load_tile = [&](int it, int buf) {
        int p  = it / kIters;
        int kb = it - p * kIters;
        int k0 = kb << 5;
        int aoff = (p == 1) ? K : 0;
        const fp16* ga = A + (size_t)(m0 + arow) * lda + aoff + k0 + acc0;
        cp16c(&sA[buf][arow][acc0],     ga);
        cp16c(&sA[buf][arow][acc0 + 8], ga + 8);
        const fp16* gb = W + (size_t)(k0 + brow) * N + n0 + bcc0;
        cp16c(&sB[buf][brow][bcc0],     gb);
        cp16c(&sB[buf][brow][bcc0 + 8], gb + 8);
        cp_commit();
    };

    load_tile(0, 0);

    for (int it = 0; it < T; ++it) {
        const int buf = it & 1;
        if (it + 1 < T) { load_tile(it + 1, buf ^ 1); cp_wait1(); }
        else            { cp_wait0(); }
        __syncthreads();

#pragma unroll
        for (int kk = 0; kk < 2; ++kk) {
            uint32_t afrag[2][4];
#pragma unroll
            for (int mt = 0; mt < 2; ++mt) {
                int r = wm * 32 + mt * 16 + (lane & 15);
                int c = kk * 16 + ((lane >> 4) << 3);
                LDSM_X4(afrag[mt][0], afrag[mt][1], afrag[mt][2], afrag[mt][3],
                        smem_u32(&sA[buf][r][c]));
            }
            uint32_t bfrag[8][2];
#pragma unroll
            for (int tp = 0; tp < 4; ++tp) {
                int g = lane >> 3, lr = lane & 7;
                int row = kk * 16 + ((g & 1) << 3) + lr;
                int col = wn * 64 + tp * 16 + ((g >> 1) << 3);
                uint32_t r0, r1, r2, r3;
                LDSM_X4T(r0, r1, r2, r3, smem_u32(&sB[buf][row][col]));
                bfrag[tp * 2][0] = r0;     bfrag[tp * 2][1] = r1;
                bfrag[tp * 2 + 1][0] = r2; bfrag[tp * 2 + 1][1] = r3;
            }
#pragma unroll
            for (int mt = 0; mt < 2; ++mt)
#pragma unroll
                for (int nt = 0; nt < 8; ++nt)
                    mma16816(acc[mt][nt], afrag[mt], bfrag[nt]);
        }
        __syncthreads();
    }

    // epilogue
    const int r0 = lane >> 2, c0 = (lane & 3) * 2;
#pragma unroll
    for (int mt = 0; mt < 2; ++mt) {
#pragma unroll
        for (int half = 0; half < 2; ++half) {
            const int m = m0 + wm * 32 + mt * 16 + r0 + half * 8;
            const int et = m >> 14;
#pragma unroll
            for (int nt = 0; nt < 8; ++nt) {
                const int n = n0 + wn * 64 + nt * 8 + c0;
                float v0 = acc[mt][nt][half * 2 + 0] + bias[n];
                float v1 = acc[mt][nt][half * 2 + 1] + bias[n + 1];
                if (EPI == 2) {
                    v0 += aux[(size_t)et * N + n];
                    v1 += aux[(size_t)et * N + n + 1];
                }
                if (EPI == 1 || EPI == 2) { v0 = fmaxf(v0, 0.f); v1 = fmaxf(v1, 0.f); }
                if (EPI == 3) {
                    fp162 mpair = *(const fp162*)(auxh + (size_t)m * N + n);
                    float2 mf = __half22float2(mpair);
                    v0 = mf.x * sigf(v0);
                    v1 = mf.y * sigf(v1);
                }
                if (OUT & 1) {
                    float2 fv = {v0, v1};
                    *(float2*)&C[(size_t)m * N + n] = fv;
                }
                if (OUT & 2) {
                    fp16* base = E + (size_t)m * 2 * N;
                    *(fp162*)(base + n) = __halves2half2(
                        __float2half_rn(v0), __float2half_rn(v1));
                }
                if (OUT & 4) {
                    *(fp162*)(E + (size_t)m * N + n) = __halves2half2(
                        __float2half_rn(v0), __float2half_rn(v1));
                }
            }
        }
    }
}

// ---------------------------------------------------------------------------
// Conversion / elementwise kernels
// ---------------------------------------------------------------------------

__global__ void cvt_w_k(const float* __restrict__ W, fp16* __restrict__ E, int KN)
{
    int gid = blockIdx.x * blockDim.x + threadIdx.x;
    if (gid * 4 >= KN) return;
    float4 v = *(const float4*)(W + (size_t)gid * 4);
    hi4(v, E + (size_t)gid * 4);
}

// GRU weight (3H,H) row-major -> transposed plain fp16 [H, 3H]
__global__ void cvt_w_gru_k(const float* __restrict__ Wg, fp16* __restrict__ E)
{
    int gid = blockIdx.x * blockDim.x + threadIdx.x;
    if (gid >= HH * G3H) return;
    int k = gid / G3H, j = gid - k * G3H;
    E[gid] = __float2half_rn(Wg[(size_t)j * HH + k]);
}

__global__ void cvt_text_k(const float* __restrict__ X)
{
    int gid = blockIdx.x * blockDim.x + threadIdx.x;
    if (gid >= BB * (TT / 4)) return;
    int m = gid / (TT / 4), q = gid - m * (TT / 4);
    float4 v = *(const float4*)(X + (size_t)m * TT + q * 4);
    hi4(v, g_text_e + (size_t)m * 2 * TT + q * 4);
}

// gather node embeddings for ACTIVE nodes: A, Event, B (3B rows)
__global__ void gather_emb_k(const int* __restrict__ a, const int* __restrict__ ev,
                             const int* __restrict__ b,
                             const float* __restrict__ ent)
{
    int gid = blockIdx.x * blockDim.x + threadIdx.x;
    if (gid >= 3 * BB * (DD / 4)) return;
    int row = gid >> 6, c4 = (gid & 63) * 4;
    int sel = row >> 14, r = row & (BB - 1);
    int id = (sel == 0) ? a[r] : (sel == 1) ? ev[r] : b[r];
    float4 v = *(const float4*)(ent + (size_t)id * DD + c4);
    if (sel == 1) {
        float4 tv = *(const float4*)(g_tx + (size_t)r * DD + c4);
        v.x += tv.x; v.y += tv.y; v.z += tv.z; v.w += tv.w;
    }
    hi4(v, g_emb4_e + (size_t)row * 2 * DD + c4);
}

// diff over 2B live edges (src=row, dst=row+B)
__global__ void diff_cvt_k()
{
    int gid = blockIdx.x * blockDim.x + threadIdx.x;
    if (gid >= 2 * BB * (HH / 4)) return;
    int row = gid >> 7, c = (gid & 127) * 4;
    float4 s = *(const float4*)(g_state + (size_t)row * HH + c);
    float4 d = *(const float4*)(g_state + (size_t)(row + BB) * HH + c);
    s.x -= d.x; s.y -= d.y; s.z -= d.z; s.w -= d.w;
    hi4(s, g_diff_e + (size_t)row * 2 * HH + c);
}

// relu over 3B active nodes
__global__ void relu_state_k()
{
    int gid = blockIdx.x * blockDim.x + threadIdx.x;
    if (gid >= 3 * BB * (HH / 4)) return;
    int row = gid >> 7, c = (gid & 127) * 4;
    float4 v = *(float4*)(g_state + (size_t)row * HH + c);
    v.x = fmaxf(v.x, 0.f); v.y = fmaxf(v.y, 0.f);
    v.z = fmaxf(v.z, 0.f); v.w = fmaxf(v.w, 0.f);
    *(float4*)(g_state + (size_t)row * HH + c) = v;
    hi4(v, g_state_e + (size_t)row * 2 * HH + c);
}

// GRU update over 3B active nodes; gi/gh read as fp16
__global__ void gru_k(const float* __restrict__ bih)
{
    int gid = blockIdx.x * blockDim.x + threadIdx.x;
    if (gid >= 3 * BB * (HH / 4)) return;
    int m = gid >> 7, c = (gid & 127) * 4;

    const fp16* ghr = g_gh_h + (size_t)m * G3H;
    float4 hr = ld4h(ghr + c);
    float4 hz = ld4h(ghr + HH + c);
    float4 hn = ld4h(ghr + 2 * HH + c);

    float4 ir, iz, in_;
    if (m < BB) {   // A nodes: no incoming edges -> gi = bih
        ir  = *(const float4*)(bih + c);
        iz  = *(const float4*)(bih + HH + c);
        in_ = *(const float4*)(bih + 2 * HH + c);
    } else {        // Event / B nodes: gi row = m - B
        const fp16* gir = g_gi_h + (size_t)(m - BB) * G3H;
        ir  = ld4h(gir + c);
        iz  = ld4h(gir + HH + c);
        in_ = ld4h(gir + 2 * HH + c);
    }
    float4 old = *(const float4*)(g_state + (size_t)m * HH + c);

    float4 out;
    { float r = sigf(ir.x + hr.x), z = sigf(iz.x + hz.x);
      float n = tanhf(in_.x + r * hn.x); out.x = (1.f - z) * n + z * old.x; }
    { float r = sigf(ir.y + hr.y), z = sigf(iz.y + hz.y);
      float n = tanhf(in_.y + r * hn.y); out.y = (1.f - z) * n + z * old.y; }
    { float r = sigf(ir.z + hr.z), z = sigf(iz.z + hz.z);
      float n = tanhf(in_.z + r * hn.z); out.z = (1.f - z) * n + z * old.z; }
    { float r = sigf(ir.w + hr.w), z = sigf(iz.w + hz.w);
      float n = tanhf(in_.w + r * hn.w); out.w = (1.f - z) * n + z * old.w; }

    *(float4*)(g_state + (size_t)m * HH + c) = out;
    hi4(out, g_state_e + (size_t)m * 2 * HH + c);
}

// head diff -> ext [B, 2H] (hi only)
__global__ void dd_cvt_k()
{
    int gid = blockIdx.x * blockDim.x + threadIdx.x;
    if (gid >= BB * (HH / 4)) return;
    int row = gid >> 7, c = (gid & 127) * 4;
    float4 a = *(const float4*)(g_state + (size_t)row * HH + c);
    float4 b = *(const float4*)(g_state + (size_t)(row + 2 * BB) * HH + c);
    a.x -= b.x; a.y -= b.y; a.z -= b.z; a.w -= b.w;
    hi4(a, g_ddv_e + (size_t)row * 2 * HH + c);
}

// final head: out[B,32] = hh[B,512] @ W2[512,32] + b2
__global__ void head2_k(const float* __restrict__ W2, const float* __restrict__ b2,
                        float* __restrict__ out)
{
    int r = threadIdx.x >> 5, col = threadIdx.x & 31;
    int row = blockIdx.x * 8 + r;
    const float* h = g_hh + (size_t)row * HH;
    float acc = b2[col];
#pragma unroll 8
    for (int k = 0; k < HH; k++)
        acc = fmaf(h[k], W2[k * RR + col], acc);
    out[(size_t)row * RR + col] = acc;
}

// ---------------------------------------------------------------------------
// Host launch
// ---------------------------------------------------------------------------
template<int EPI, int OUT, int PASSES>
static void rg(const fp16* A, const fp16* W, float* C, fp16* E,
               const float* bias, const float* aux, const fp16* auxh,
               int M, int N, int K)
{
    dim3 grid(N / 128, M / 128);
    hgemm_k<EPI, OUT, PASSES><<<grid, 256>>>(A, W, C, E, bias, aux, auxh, M, N, K);
}

extern "C" void kernel_launch(void* const* d_in, const int* in_sizes, int n_in,
                              void* d_out, int out_size)
{
    const int*   a_ids   = (const int*)  d_in[0];
    const int*   ev_ids  = (const int*)  d_in[1];
    const int*   b_ids   = (const int*)  d_in[2];
    const float* text_ab = (const float*)d_in[4];
    const float* ent     = (const float*)d_in[5];
    const float* text_W  = (const float*)d_in[6];
    const float* text_b  = (const float*)d_in[7];
    const float* proj_W  = (const float*)d_in[8];
    const float* proj_b  = (const float*)d_in[9];
    const float* msg_W1  = (const float*)d_in[10];
    const float* msg_b1  = (const float*)d_in[11];
    const float* msg_W2  = (const float*)d_in[12];
    const float* msg_b2  = (const float*)d_in[13];
    const float* att_W1  = (const float*)d_in[14];
    const float* att_b1  = (const float*)d_in[15];
    const float* att_W2  = (const float*)d_in[16];
    const float* att_b2  = (const float*)d_in[17];
    const float* gru_Wih = (const float*)d_in[18];
    const float* gru_Whh = (const float*)d_in[19];
    const float* gru_bih = (const float*)d_in[20];
    const float* gru_bhh = (const float*)d_in[21];
    const float* head_W1 = (const float*)d_in[22];
    const float* head_b1 = (const float*)d_in[23];
    const float* head_W2 = (const float*)d_in[24];
    const float* head_b2 = (const float*)d_in[25];
    float* out = (float*)d_out;

    float *tx, *state, *hh;
    fp16 *msg_h, *gi_h, *gh_h;
    fp16 *text_e, *emb4_e, *state_e, *diff_e, *hidm_e, *hida_e, *msgatt_e, *ddv_e;
    fp16 *textW, *projW, *msgW1h, *msgW2h, *attW1h, *attW2h, *Wihh, *Whhh, *headW1h;
    cudaGetSymbolAddress((void**)&tx,       g_tx);
    cudaGetSymbolAddress((void**)&state,    g_state);
    cudaGetSymbolAddress((void**)&hh,       g_hh);
    cudaGetSymbolAddress((void**)&msg_h,    g_msg_h);
    cudaGetSymbolAddress((void**)&gi_h,     g_gi_h);
    cudaGetSymbolAddress((void**)&gh_h,     g_gh_h);
    cudaGetSymbolAddress((void**)&text_e,   g_text_e);
    cudaGetSymbolAddress((void**)&emb4_e,   g_emb4_e);
    cudaGetSymbolAddress((void**)&state_e,  g_state_e);
    cudaGetSymbolAddress((void**)&diff_e,   g_diff_e);
    cudaGetSymbolAddress((void**)&hidm_e,   g_hidm_e);
    cudaGetSymbolAddress((void**)&hida_e,   g_hida_e);
    cudaGetSymbolAddress((void**)&msgatt_e, g_msgatt_e);
    cudaGetSymbolAddress((void**)&ddv_e,    g_ddv_e);
    cudaGetSymbolAddress((void**)&textW,    g_textW_h);
    cudaGetSymbolAddress((void**)&projW,    g_projW_h);
    cudaGetSymbolAddress((void**)&msgW1h,   g_msgW1_h);
    cudaGetSymbolAddress((void**)&msgW2h,   g_msgW2_h);
    cudaGetSymbolAddress((void**)&attW1h,   g_attW1_h);
    cudaGetSymbolAddress((void**)&attW2h,   g_attW2_h);
    cudaGetSymbolAddress((void**)&Wihh,     g_Wih_h);
    cudaGetSymbolAddress((void**)&Whhh,     g_Whh_h);
    cudaGetSymbolAddress((void**)&headW1h,  g_headW1_h);

    auto cvw = [](const float* W, fp16* E, int KN) {
        cvt_w_k<<<(KN / 4 + 255) / 256, 256>>>(W, E, KN);
    };

    cvw(text_W, textW, TT * DD);
    cvt_text_k<<<(BB * (TT / 4) + 255) / 256, 256>>>(text_ab);
    rg<1, 1, 1>(text_e, textW, tx, nullptr, text_b, nullptr, nullptr, BB, DD, TT);
    cvw(proj_W, projW, DD * HH);
    gather_emb_k<<<(3 * BB * (DD / 4) + 255) / 256, 256>>>(a_ids, ev_ids, b_ids, ent);
    rg<1, 3, 1>(emb4_e, projW, state, state_e, proj_b, nullptr, nullptr, 3 * BB, HH, DD);

    for (int l = 0; l < 2; l++) {
        cvw(msg_W1 + (size_t)l * 520 * HH,     msgW1h + (size_t)l * HH * HH, HH * HH);
        cvw(msg_W2 + (size_t)l * HH * HH,      msgW2h + (size_t)l * HH * HH, HH * HH);
        cvw(att_W1 + (size_t)l * 520 * (HH/2), attW1h + (size_t)l * HH * (HH/2), HH * (HH/2));
        cvw(att_W2 + (size_t)l * (HH/2) * HH,  attW2h + (size_t)l * (HH/2) * HH, (HH/2) * HH);
        int tot = HH * G3H;
        cvt_w_gru_k<<<(tot + 255) / 256, 256>>>(gru_Wih + (size_t)l * G3H * HH,
                                                Wihh + (size_t)l * HH * G3H);
        cvt_w_gru_k<<<(tot + 255) / 256, 256>>>(gru_Whh + (size_t)l * G3H * HH,
                                                Whhh + (size_t)l * HH * G3H);
    }
    cvw(head_W1, headW1h, HH * HH);

    const int ew = 3 * BB * (HH / 4);   // 3B active nodes
    const int ed = 2 * BB * (HH / 4);   // 2B live edges

    for (int ii = 0; ii < 2; ii++) {
        if (ii) relu_state_k<<<(ew + 255) / 256, 256>>>();
        const float* mW1 = msg_W1 + (size_t)ii * 520 * HH;
        const float* aW1 = att_W1 + (size_t)ii * 520 * (HH / 2);
        for (int p = 0; p < 2; p++) {
            diff_cvt_k<<<(ed + 255) / 256, 256>>>();
            // hidm_e = relu(diff @ W1 + b1 + edgebias)            [2B edges]
            rg<2, 2, 1>(diff_e, msgW1h + (size_t)ii * HH * HH,
                        nullptr, hidm_e, msg_b1 + ii * HH, mW1 + 512 * HH, nullptr,
                        2 * BB, HH, HH);
            // msg (fp16) = hidm @ W2 + b2
            rg<0, 4, 1>(hidm_e, msgW2h + (size_t)ii * HH * HH,
                        nullptr, msg_h, msg_b2 + ii * HH, nullptr, nullptr,
                        2 * BB, HH, HH);
            // hida_e = relu(diff @ attW1 + b + edgebias)
            rg<2, 2, 1>(diff_e, attW1h + (size_t)ii * HH * (HH/2),
                        nullptr, hida_e, att_b1 + ii * (HH / 2), aW1 + 512 * (HH / 2),
                        nullptr, 2 * BB, HH / 2, HH);
            // msgatt_e = msg * sigmoid(hida @ attW2 + b)
            rg<3, 2, 1>(hida_e, attW2h + (size_t)ii * (HH/2) * HH,
                        nullptr, msgatt_e, att_b2 + ii * HH, nullptr, msg_h,
                        2 * BB, HH, HH / 2);
            // gi (fp16) = msgatt @ Wih^T + bih  (rows -> nodes B..3B)
            rg<0, 4, 1>(msgatt_e, Wihh + (size_t)ii * HH * G3H,
                        nullptr, gi_h, gru_bih + ii * G3H, nullptr, nullptr,
                        2 * BB, G3H, HH);
            // gh (fp16) = state @ Whh^T + bhh   (3B active nodes)
            rg<0, 4, 1>(state_e, Whhh + (size_t)ii * HH * G3H,
                        nullptr, gh_h, gru_bhh + ii * G3H, nullptr, nullptr,
                        3 * BB, G3H, HH);
            // GRU update over 3B nodes
            gru_k<<<(ew + 255) / 256, 256>>>(gru_bih + ii * G3H);
        }
    }

    // ---- head ----
    dd_cvt_k<<<(BB * (HH / 4) + 255) / 256, 256>>>();
    rg<1, 1, 1>(ddv_e, headW1h, hh, nullptr, head_b1, nullptr, nullptr, BB, HH, HH);
    head2_k<<<BB / 8, 256>>>(head_W2, head_b2, out);
}

// round 17
// speedup vs baseline: 2.7433x; 1.0336x over previous
#include <cuda_runtime.h>
#include <cuda_fp16.h>
#include <math.h>
#include <stdint.h>
#include <stddef.h>

// Problem constants
#define BB   16384            // batch / paths
#define DD   256              // embedding dim
#define HH   512              // hidden dim
#define TT   768              // text dim
#define RR   32               // relation classes
#define G3H  1536             // 3*H

// C nodes (3B:4B) are dead. Active nodes: A(0:B), Event(B:2B), B(2B:3B).
// 3B nodes, 2B edges (A->Event, Event->B); src=row, dst=row+B.

typedef __half  fp16;
typedef __half2 fp162;

// ---------------------------------------------------------------------------
// Scratch. "_e": ext fp16 [M,2K] layout (hi half live). gi/gh/msg fp16.
// ---------------------------------------------------------------------------
__device__ __align__(128) float g_tx   [(size_t)BB * DD];
__device__ __align__(128) float g_state[(size_t)4 * BB * HH];
__device__ __align__(128) float g_hh   [(size_t)BB * HH];

__device__ __align__(128) fp16 g_msg_h [(size_t)3 * BB * HH];
__device__ __align__(128) fp16 g_gi_h  [(size_t)3 * BB * G3H];
__device__ __align__(128) fp16 g_gh_h  [(size_t)4 * BB * G3H];

__device__ __align__(128) fp16 g_text_e  [(size_t)BB * 2 * TT];
__device__ __align__(128) fp16 g_emb4_e  [(size_t)4 * BB * 2 * DD];
__device__ __align__(128) fp16 g_state_e [(size_t)4 * BB * 2 * HH];
__device__ __align__(128) fp16 g_diff_e  [(size_t)3 * BB * 2 * HH];
__device__ __align__(128) fp16 g_hidm_e  [(size_t)3 * BB * 2 * HH];
__device__ __align__(128) fp16 g_hida_e  [(size_t)3 * BB * HH];
__device__ __align__(128) fp16 g_msgatt_e[(size_t)3 * BB * 2 * HH];
__device__ __align__(128) fp16 g_ddv_e   [(size_t)BB * 2 * HH];

// plain fp16 weights [K,N]
__device__ __align__(128) fp16 g_textW_h [(size_t)TT * DD];
__device__ __align__(128) fp16 g_projW_h [(size_t)DD * HH];
__device__ __align__(128) fp16 g_msgW1_h [2][(size_t)HH * HH];
__device__ __align__(128) fp16 g_msgW2_h [2][(size_t)HH * HH];
__device__ __align__(128) fp16 g_attW1_h [2][(size_t)HH * (HH/2)];
__device__ __align__(128) fp16 g_attW2_h [2][(size_t)(HH/2) * HH];
__device__ __align__(128) fp16 g_Wih_h   [2][(size_t)HH * G3H];
__device__ __align__(128) fp16 g_Whh_h   [2][(size_t)HH * G3H];
__device__ __align__(128) fp16 g_headW1_h[(size_t)HH * HH];

// ---------------------------------------------------------------------------
// Small helpers
// ---------------------------------------------------------------------------
__device__ __forceinline__ uint32_t smem_u32(const void* p) {
    return (uint32_t)__cvta_generic_to_shared(p);
}
__device__ __forceinline__ void cp16c(void* s, const void* g) {
    asm volatile("cp.async.cg.shared.global [%0], [%1], 16;\n"
                 :: "r"(smem_u32(s)), "l"(g));
}
__device__ __forceinline__ void cp_commit() {
    asm volatile("cp.async.commit_group;\n");
}
__device__ __forceinline__ void cp_wait0() {
    asm volatile("cp.async.wait_group 0;\n");
}
__device__ __forceinline__ void cp_wait1() {
    asm volatile("cp.async.wait_group 1;\n");
}
#define LDSM_X4(r0,r1,r2,r3,addr) \
    asm volatile("ldmatrix.sync.aligned.m8n8.x4.shared.b16 {%0,%1,%2,%3}, [%4];" \
        : "=r"(r0),"=r"(r1),"=r"(r2),"=r"(r3) : "r"(addr))
#define LDSM_X4T(r0,r1,r2,r3,addr) \
    asm volatile("ldmatrix.sync.aligned.m8n8.x4.trans.shared.b16 {%0,%1,%2,%3}, [%4];" \
        : "=r"(r0),"=r"(r1),"=r"(r2),"=r"(r3) : "r"(addr))
__device__ __forceinline__ void mma16816(float* d, const uint32_t* a, const uint32_t* b) {
    asm volatile(
        "mma.sync.aligned.m16n8k16.row.col.f32.f16.f16.f32 "
        "{%0,%1,%2,%3},{%4,%5,%6,%7},{%8,%9},{%0,%1,%2,%3};"
        : "+f"(d[0]), "+f"(d[1]), "+f"(d[2]), "+f"(d[3])
        : "r"(a[0]), "r"(a[1]), "r"(a[2]), "r"(a[3]), "r"(b[0]), "r"(b[1]));
}

// fast approximations (MUFU-based): rel err ~2^-11, same order as fp16 floor
__device__ __forceinline__ float fast_sig(float x) {
    float t;
    asm("ex2.approx.f32 %0, %1;" : "=f"(t) : "f"(-x * 1.4426950408889634f));
    float r;
    asm("rcp.approx.f32 %0, %1;" : "=f"(r) : "f"(1.f + t));
    return r;
}
__device__ __forceinline__ float fast_tanh(float x) {
    float y;
    asm("tanh.approx.f32 %0, %1;" : "=f"(y) : "f"(x));
    return y;
}

// write 4 fp32 values as fp16
__device__ __forceinline__ void hi4(float4 v, fp16* hp) {
    ((fp162*)hp)[0] = __halves2half2(__float2half_rn(v.x), __float2half_rn(v.y));
    ((fp162*)hp)[1] = __halves2half2(__float2half_rn(v.z), __float2half_rn(v.w));
}
// read 4 fp16 -> float4
__device__ __forceinline__ float4 ld4h(const fp16* p) {
    fp162 a = ((const fp162*)p)[0], b = ((const fp162*)p)[1];
    float2 fa = __half22float2(a), fb = __half22float2(b);
    return make_float4(fa.x, fa.y, fb.x, fb.y);
}

// ---------------------------------------------------------------------------
// fp16 tensor-core GEMM (1-pass).
// A: [M, 2K] ext fp16 (hi in cols [0,K)), W: [K, N] plain fp16.
// EPI: 0 = +bias, 1 = relu(+bias), 2 = relu(+bias + aux[m>>14][n]),
//      3 = auxh[m,n] * sigmoid(+bias)   (auxh = fp16 multiplier)
// OUT: 1 = fp32 C row-major; 2 = ext fp16 E (hi half); 4 = plain fp16 E
// Tile 128x128x32, 256 threads.
// ---------------------------------------------------------------------------
template<int EPI, int OUT, int PASSES>
__global__ __launch_bounds__(256)
void hgemm_k(const fp16* __restrict__ A, const fp16* __restrict__ W,
             float* __restrict__ C, fp16* __restrict__ E,
             const float* __restrict__ bias, const float* __restrict__ aux,
             const fp16* __restrict__ auxh,
             int M, int N, int K)
{
    __shared__ __align__(16) fp16 sA[2][128][40];   // 32 + 8 pad
    __shared__ __align__(16) fp16 sB[2][32][136];   // 128 + 8 pad

    const int tid = threadIdx.x;
    const int m0 = blockIdx.y * 128, n0 = blockIdx.x * 128;
    const int warp = tid >> 5, lane = tid & 31;
    const int wm = warp & 3, wn = warp >> 2;

    const int kIters = K >> 5;
    const int T = PASSES * kIters;
    const size_t lda = 2 * (size_t)K;

    float acc[2][8][4];
#pragma unroll
    for (int i = 0; i < 2; i++)
#pragma unroll
        for (int j = 0; j < 8; j++)
#pragma unroll
            for (int q = 0; q < 4; q++) acc[i][j][q] = 0.f;

    const int arow = tid >> 1, acc0 = (tid & 1) * 16;
    const int brow = tid >> 3, bcc0 = (tid & 7) * 16;

    auto load_tile = [&](int it, int buf) {
        int p  = it / kIters;
        int kb = it - p * kIters;
        int k0 = kb << 5;
        int aoff = (p == 1) ? K : 0;
        const fp16* ga = A + (size_t)(m0 + arow) * lda + aoff + k0 + acc0;
        cp16c(&sA[buf][arow][acc0],     ga);
        cp16c(&sA[buf][arow][acc0 + 8], ga + 8);
        const fp16* gb = W + (size_t)(k0 + brow) * N + n0 + bcc0;
        cp16c(&sB[buf][brow][bcc0],     gb);
        cp16c(&sB[buf][brow][bcc0 + 8], gb + 8);
        cp_commit();
    };

    load_tile(0, 0);

    for (int it = 0; it < T; ++it) {
        const int buf = it & 1;
        if (it + 1 < T) { load_tile(it + 1, buf ^ 1); cp_wait1(); }
        else            { cp_wait0(); }
        __syncthreads();

#pragma unroll
        for (int kk = 0; kk < 2; ++kk) {
            uint32_t afrag[2][4];
#pragma unroll
            for (int mt = 0; mt < 2; ++mt) {
                int r = wm * 32 + mt * 16 + (lane & 15);
                int c = kk * 16 + ((lane >> 4) << 3);
                LDSM_X4(afrag[mt][0], afrag[mt][1], afrag[mt][2], afrag[mt][3],
                        smem_u32(&sA[buf][r][c]));
            }
            uint32_t bfrag[8][2];
#pragma unroll
            for (int tp = 0; tp < 4; ++tp) {
                int g = lane >> 3, lr = lane & 7;
                int row = kk * 16 + ((g & 1) << 3) + lr;
                int col = wn * 64 + tp * 16 + ((g >> 1) << 3);
                uint32_t r0, r1, r2, r3;
                LDSM_X4T(r0, r1, r2, r3, smem_u32(&sB[buf][row][col]));
                bfrag[tp * 2][0] = r0;     bfrag[tp * 2][1] = r1;
                bfrag[tp * 2 + 1][0] = r2; bfrag[tp * 2 + 1][1] = r3;
            }
#pragma unroll
            for (int mt = 0; mt < 2; ++mt)
#pragma unroll
                for (int nt = 0; nt < 8; ++nt)
                    mma16816(acc[mt][nt], afrag[mt], bfrag[nt]);
        }
        __syncthreads();
    }

    // epilogue
    const int r0 = lane >> 2, c0 = (lane & 3) * 2;
#pragma unroll
    for (int mt = 0; mt < 2; ++mt) {
#pragma unroll
        for (int half = 0; half < 2; ++half) {
            const int m = m0 + wm * 32 + mt * 16 + r0 + half * 8;
            const int et = m >> 14;
#pragma unroll
            for (int nt = 0; nt < 8; ++nt) {
                const int n = n0 + wn * 64 + nt * 8 + c0;
                float v0 = acc[mt][nt][half * 2 + 0] + bias[n];
                float v1 = acc[mt][nt][half * 2 + 1] + bias[n + 1];
                if (EPI == 2) {
                    v0 += aux[(size_t)et * N + n];
                    v1 += aux[(size_t)et * N + n + 1];
                }
                if (EPI == 1 || EPI == 2) { v0 = fmaxf(v0, 0.f); v1 = fmaxf(v1, 0.f); }
                if (EPI == 3) {
                    fp162 mpair = *(const fp162*)(auxh + (size_t)m * N + n);
                    float2 mf = __half22float2(mpair);
                    v0 = mf.x * fast_sig(v0);
                    v1 = mf.y * fast_sig(v1);
                }
                if (OUT & 1) {
                    float2 fv = {v0, v1};
                    *(float2*)&C[(size_t)m * N + n] = fv;
                }
                if (OUT & 2) {
                    fp16* base = E + (size_t)m * 2 * N;
                    *(fp162*)(base + n) = __halves2half2(
                        __float2half_rn(v0), __float2half_rn(v1));
                }
                if (OUT & 4) {
                    *(fp162*)(E + (size_t)m * N + n) = __halves2half2(
                        __float2half_rn(v0), __float2half_rn(v1));
                }
            }
        }
    }
}

// ---------------------------------------------------------------------------
// Conversion / elementwise kernels
// ---------------------------------------------------------------------------

__global__ void cvt_w_k(const float* __restrict__ W, fp16* __restrict__ E, int KN)
{
    int gid = blockIdx.x * blockDim.x + threadIdx.x;
    if (gid * 4 >= KN) return;
    float4 v = *(const float4*)(W + (size_t)gid * 4);
    hi4(v, E + (size_t)gid * 4);
}

// GRU weight (3H,H) row-major -> transposed plain fp16 [H, 3H]
__global__ void cvt_w_gru_k(const float* __restrict__ Wg, fp16* __restrict__ E)
{
    int gid = blockIdx.x * blockDim.x + threadIdx.x;
    if (gid >= HH * G3H) return;
    int k = gid / G3H, j = gid - k * G3H;
    E[gid] = __float2half_rn(Wg[(size_t)j * HH + k]);
}

__global__ void cvt_text_k(const float* __restrict__ X)
{
    int gid = blockIdx.x * blockDim.x + threadIdx.x;
    if (gid >= BB * (TT / 4)) return;
    int m = gid / (TT / 4), q = gid - m * (TT / 4);
    float4 v = *(const float4*)(X + (size_t)m * TT + q * 4);
    hi4(v, g_text_e + (size_t)m * 2 * TT + q * 4);
}

// gather node embeddings for ACTIVE nodes: A, Event, B (3B rows)
__global__ void gather_emb_k(const int* __restrict__ a, const int* __restrict__ ev,
                             const int* __restrict__ b,
                             const float* __restrict__ ent)
{
    int gid = blockIdx.x * blockDim.x + threadIdx.x;
    if (gid >= 3 * BB * (DD / 4)) return;
    int row = gid >> 6, c4 = (gid & 63) * 4;
    int sel = row >> 14, r = row & (BB - 1);
    int id = (sel == 0) ? a[r] : (sel == 1) ? ev[r] : b[r];
    float4 v = *(const float4*)(ent + (size_t)id * DD + c4);
    if (sel == 1) {
        float4 tv = *(const float4*)(g_tx + (size_t)r * DD + c4);
        v.x += tv.x; v.y += tv.y; v.z += tv.z; v.w += tv.w;
    }
    hi4(v, g_emb4_e + (size_t)row * 2 * DD + c4);
}

// diff over 2B live edges (src=row, dst=row+B)
__global__ void diff_cvt_k()
{
    int gid = blockIdx.x * blockDim.x + threadIdx.x;
    if (gid >= 2 * BB * (HH / 4)) return;
    int row = gid >> 7, c = (gid & 127) * 4;
    float4 s = *(const float4*)(g_state + (size_t)row * HH + c);
    float4 d = *(const float4*)(g_state + (size_t)(row + BB) * HH + c);
    s.x -= d.x; s.y -= d.y; s.z -= d.z; s.w -= d.w;
    hi4(s, g_diff_e + (size_t)row * 2 * HH + c);
}

// GRU update over 3B active nodes; gi/gh read fp16; optional fused relu
// (RELU=1 fuses the layer-boundary relu of the NEXT layer: state <- relu(gru))
template<int RELU>
__global__ void gru_k(const float* __restrict__ bih)
{
    int gid = blockIdx.x * blockDim.x + threadIdx.x;
    if (gid >= 3 * BB * (HH / 4)) return;
    int m = gid >> 7, c = (gid & 127) * 4;

    const fp16* ghr = g_gh_h + (size_t)m * G3H;
    float4 hr = ld4h(ghr + c);
    float4 hz = ld4h(ghr + HH + c);
    float4 hn = ld4h(ghr + 2 * HH + c);

    float4 ir, iz, in_;
    if (m < BB) {   // A nodes: no incoming edges -> gi = bih
        ir  = *(const float4*)(bih + c);
        iz  = *(const float4*)(bih + HH + c);
        in_ = *(const float4*)(bih + 2 * HH + c);
    } else {        // Event / B nodes: gi row = m - B
        const fp16* gir = g_gi_h + (size_t)(m - BB) * G3H;
        ir  = ld4h(gir + c);
        iz  = ld4h(gir + HH + c);
        in_ = ld4h(gir + 2 * HH + c);
    }
    float4 old = *(const float4*)(g_state + (size_t)m * HH + c);

    float4 out;
    { float r = fast_sig(ir.x + hr.x), z = fast_sig(iz.x + hz.x);
      float n = fast_tanh(in_.x + r * hn.x); out.x = (1.f - z) * n + z * old.x; }
    { float r = fast_sig(ir.y + hr.y), z = fast_sig(iz.y + hz.y);
      float n = fast_tanh(in_.y + r * hn.y); out.y = (1.f - z) * n + z * old.y; }
    { float r = fast_sig(ir.z + hr.z), z = fast_sig(iz.z + hz.z);
      float n = fast_tanh(in_.z + r * hn.z); out.z = (1.f - z) * n + z * old.z; }
    { float r = fast_sig(ir.w + hr.w), z = fast_sig(iz.w + hz.w);
      float n = fast_tanh(in_.w + r * hn.w); out.w = (1.f - z) * n + z * old.w; }

    if (RELU) {
        out.x = fmaxf(out.x, 0.f); out.y = fmaxf(out.y, 0.f);
        out.z = fmaxf(out.z, 0.f); out.w = fmaxf(out.w, 0.f);
    }

    *(float4*)(g_state + (size_t)m * HH + c) = out;
    hi4(out, g_state_e + (size_t)m * 2 * HH + c);
}

// head diff -> ext [B, 2H] (hi only)
__global__ void dd_cvt_k()
{
    int gid = blockIdx.x * blockDim.x + threadIdx.x;
    if (gid >= BB * (HH / 4)) return;
    int row = gid >> 7, c = (gid & 127) * 4;
    float4 a = *(const float4*)(g_state + (size_t)row * HH + c);
    float4 b = *(const float4*)(g_state + (size_t)(row + 2 * BB) * HH + c);
    a.x -= b.x; a.y -= b.y; a.z -= b.z; a.w -= b.w;
    hi4(a, g_ddv_e + (size_t)row * 2 * HH + c);
}

// final head: out[B,32] = hh[B,512] @ W2[512,32] + b2
__global__ void head2_k(const float* __restrict__ W2, const float* __restrict__ b2,
                        float* __restrict__ out)
{
    int r = threadIdx.x >> 5, col = threadIdx.x & 31;
    int row = blockIdx.x * 8 + r;
    const float* h = g_hh + (size_t)row * HH;
    float acc = b2[col];
#pragma unroll 8
    for (int k = 0; k < HH; k++)
        acc = fmaf(h[k], W2[k * RR + col], acc);
    out[(size_t)row * RR + col] = acc;
}

// ---------------------------------------------------------------------------
// Host launch
// ---------------------------------------------------------------------------
template<int EPI, int OUT, int PASSES>
static void rg(const fp16* A, const fp16* W, float* C, fp16* E,
               const float* bias, const float* aux, const fp16* auxh,
               int M, int N, int K)
{
    dim3 grid(N / 128, M / 128);
    hgemm_k<EPI, OUT, PASSES><<<grid, 256>>>(A, W, C, E, bias, aux, auxh, M, N, K);
}

extern "C" void kernel_launch(void* const* d_in, const int* in_sizes, int n_in,
                              void* d_out, int out_size)
{
    const int*   a_ids   = (const int*)  d_in[0];
    const int*   ev_ids  = (const int*)  d_in[1];
    const int*   b_ids   = (const int*)  d_in[2];
    const float* text_ab = (const float*)d_in[4];
    const float* ent     = (const float*)d_in[5];
    const float* text_W  = (const float*)d_in[6];
    const float* text_b  = (const float*)d_in[7];
    const float* proj_W  = (const float*)d_in[8];
    const float* proj_b  = (const float*)d_in[9];
    const float* msg_W1  = (const float*)d_in[10];
    const float* msg_b1  = (const float*)d_in[11];
    const float* msg_W2  = (const float*)d_in[12];
    const float* msg_b2  = (const float*)d_in[13];
    const float* att_W1  = (const float*)d_in[14];
    const float* att_b1  = (const float*)d_in[15];
    const float* att_W2  = (const float*)d_in[16];
    const float* att_b2  = (const float*)d_in[17];
    const float* gru_Wih = (const float*)d_in[18];
    const float* gru_Whh = (const float*)d_in[19];
    const float* gru_bih = (const float*)d_in[20];
    const float* gru_bhh = (const float*)d_in[21];
    const float* head_W1 = (const float*)d_in[22];
    const float* head_b1 = (const float*)d_in[23];
    const float* head_W2 = (const float*)d_in[24];
    const float* head_b2 = (const float*)d_in[25];
    float* out = (float*)d_out;

    float *tx, *state, *hh;
    fp16 *msg_h, *gi_h, *gh_h;
    fp16 *text_e, *emb4_e, *state_e, *diff_e, *hidm_e, *hida_e, *msgatt_e, *ddv_e;
    fp16 *textW, *projW, *msgW1h, *msgW2h, *attW1h, *attW2h, *Wihh, *Whhh, *headW1h;
    cudaGetSymbolAddress((void**)&tx,       g_tx);
    cudaGetSymbolAddress((void**)&state,    g_state);
    cudaGetSymbolAddress((void**)&hh,       g_hh);
    cudaGetSymbolAddress((void**)&msg_h,    g_msg_h);
    cudaGetSymbolAddress((void**)&gi_h,     g_gi_h);
    cudaGetSymbolAddress((void**)&gh_h,     g_gh_h);
    cudaGetSymbolAddress((void**)&text_e,   g_text_e);
    cudaGetSymbolAddress((void**)&emb4_e,   g_emb4_e);
    cudaGetSymbolAddress((void**)&state_e,  g_state_e);
    cudaGetSymbolAddress((void**)&diff_e,   g_diff_e);
    cudaGetSymbolAddress((void**)&hidm_e,   g_hidm_e);
    cudaGetSymbolAddress((void**)&hida_e,   g_hida_e);
    cudaGetSymbolAddress((void**)&msgatt_e, g_msgatt_e);
    cudaGetSymbolAddress((void**)&ddv_e,    g_ddv_e);
    cudaGetSymbolAddress((void**)&textW,    g_textW_h);
    cudaGetSymbolAddress((void**)&projW,    g_projW_h);
    cudaGetSymbolAddress((void**)&msgW1h,   g_msgW1_h);
    cudaGetSymbolAddress((void**)&msgW2h,   g_msgW2_h);
    cudaGetSymbolAddress((void**)&attW1h,   g_attW1_h);
    cudaGetSymbolAddress((void**)&attW2h,   g_attW2_h);
    cudaGetSymbolAddress((void**)&Wihh,     g_Wih_h);
    cudaGetSymbolAddress((void**)&Whhh,     g_Whh_h);
    cudaGetSymbolAddress((void**)&headW1h,  g_headW1_h);

    auto cvw = [](const float* W, fp16* E, int KN) {
        cvt_w_k<<<(KN / 4 + 255) / 256, 256>>>(W, E, KN);
    };

    cvw(text_W, textW, TT * DD);
    cvt_text_k<<<(BB * (TT / 4) + 255) / 256, 256>>>(text_ab);
    rg<1, 1, 1>(text_e, textW, tx, nullptr, text_b, nullptr, nullptr, BB, DD, TT);
    cvw(proj_W, projW, DD * HH);
    gather_emb_k<<<(3 * BB * (DD / 4) + 255) / 256, 256>>>(a_ids, ev_ids, b_ids, ent);
    rg<1, 3, 1>(emb4_e, projW, state, state_e, proj_b, nullptr, nullptr, 3 * BB, HH, DD);

    for (int l = 0; l < 2; l++) {
        cvw(msg_W1 + (size_t)l * 520 * HH,     msgW1h + (size_t)l * HH * HH, HH * HH);
        cvw(msg_W2 + (size_t)l * HH * HH,      msgW2h + (size_t)l * HH * HH, HH * HH);
        cvw(att_W1 + (size_t)l * 520 * (HH/2), attW1h + (size_t)l * HH * (HH/2), HH * (HH/2));
        cvw(att_W2 + (size_t)l * (HH/2) * HH,  attW2h + (size_t)l * (HH/2) * HH, (HH/2) * HH);
        int tot = HH * G3H;
        cvt_w_gru_k<<<(tot + 255) / 256, 256>>>(gru_Wih + (size_t)l * G3H * HH,
                                                Wihh + (size_t)l * HH * G3H);
        cvt_w_gru_k<<<(tot + 255) / 256, 256>>>(gru_Whh + (size_t)l * G3H * HH,
                                                Whhh + (size_t)l * HH * G3H);
    }
    cvw(head_W1, headW1h, HH * HH);

    const int ew = 3 * BB * (HH / 4);   // 3B active nodes
    const int ed = 2 * BB * (HH / 4);   // 2B live edges

    for (int ii = 0; ii < 2; ii++) {
        const float* mW1 = msg_W1 + (size_t)ii * 520 * HH;
        const float* aW1 = att_W1 + (size_t)ii * 520 * (HH / 2);
        for (int p = 0; p < 2; p++) {
            diff_cvt_k<<<(ed + 255) / 256, 256>>>();
            // hidm_e = relu(diff @ W1 + b1 + edgebias)            [2B edges]
            rg<2, 2, 1>(diff_e, msgW1h + (size_t)ii * HH * HH,
                        nullptr, hidm_e, msg_b1 + ii * HH, mW1 + 512 * HH, nullptr,
                        2 * BB, HH, HH);
            // msg (fp16) = hidm @ W2 + b2
            rg<0, 4, 1>(hidm_e, msgW2h + (size_t)ii * HH * HH,
                        nullptr, msg_h, msg_b2 + ii * HH, nullptr, nullptr,
                        2 * BB, HH, HH);
            // hida_e = relu(diff @ attW1 + b + edgebias)
            rg<2, 2, 1>(diff_e, attW1h + (size_t)ii * HH * (HH/2),
                        nullptr, hida_e, att_b1 + ii * (HH / 2), aW1 + 512 * (HH / 2),
                        nullptr, 2 * BB, HH / 2, HH);
            // msgatt_e = msg * sigmoid(hida @ attW2 + b)
            rg<3, 2, 1>(hida_e, attW2h + (size_t)ii * (HH/2) * HH,
                        nullptr, msgatt_e, att_b2 + ii * HH, nullptr, msg_h,
                        2 * BB, HH, HH / 2);
            // gi (fp16) = msgatt @ Wih^T + bih  (rows -> nodes B..3B)
            rg<0, 4, 1>(msgatt_e, Wihh + (size_t)ii * HH * G3H,
                        nullptr, gi_h, gru_bih + ii * G3H, nullptr, nullptr,
                        2 * BB, G3H, HH);
            // gh (fp16) = state @ Whh^T + bhh   (3B active nodes)
            rg<0, 4, 1>(state_e, Whhh + (size_t)ii * HH * G3H,
                        nullptr, gh_h, gru_bhh + ii * G3H, nullptr, nullptr,
                        3 * BB, G3H, HH);
            // GRU update over 3B nodes; fuse layer-boundary relu after layer 0
            if (ii == 0 && p == 1)
                gru_k<1><<<(ew + 255) / 256, 256>>>(gru_bih + ii * G3H);
            else
                gru_k<0><<<(ew + 255) / 256, 256>>>(gru_bih + ii * G3H);
        }
    }

    // ---- head ----
    dd_cvt_k<<<(BB * (HH / 4) + 255) / 256, 256>>>();
    rg<1, 1, 1>(ddv_e, headW1h, hh, nullptr, head_b1, nullptr, nullptr, BB, HH, HH);
    head2_k<<<BB / 8, 256>>>(head_W2, head_b2, out);
}